// round 11
// baseline (speedup 1.0000x reference)
#include <cuda_runtime.h>
#include <cuda_fp16.h>
#include <cuda_bf16.h>
#include <cstdint>

#define N_NODES 50000
#define E_EDGES 800000
#define DIM     256
#define NHEAD   8
#define SCAN_BLK 1024
#define NBLK_SCAN ((N_NODES + SCAN_BLK - 1) / SCAN_BLK)   // 49

// ---------------- device scratch (allocation-free rule: use globals) -------
__device__ float  g_attr_sum[N_NODES * 2];
__device__ int    g_deg[N_NODES];
__device__ float  g_loop_attr[N_NODES * 2];
__device__ __half g_xl_h[(size_t)N_NODES * DIM];   // x @ W_l (fp16)
__device__ __half g_xr_h[(size_t)N_NODES * DIM];   // x @ W_r (fp16)
__device__ int    g_row_start[N_NODES];
__device__ int    g_fill[N_NODES];
__device__ uint4  g_csr_rec[E_EDGES];              // {src, ea0, ea1, 0} packed 16B
__device__ int    g_scan_tmp[N_NODES];
__device__ int    g_block_sums[64];
__device__ int    g_block_off[64];
__device__ __half g_x_h[(size_t)N_NODES * DIM];    // x in fp16
__device__ __half g_wl_ht[DIM * DIM];              // W_l^T in fp16 [n][k]
__device__ __half g_wr_ht[DIM * DIM];              // W_r^T in fp16 [n][k]

// ---------------- fp32 -> fp16 conversion kernels ---------------------------
__global__ void cvt_half_kernel(const float4* __restrict__ in, __half* __restrict__ out, int n4) {
    int i = blockIdx.x * blockDim.x + threadIdx.x;
    if (i >= n4) return;
    float4 v = in[i];
    __half2 h0 = __floats2half2_rn(v.x, v.y);
    __half2 h1 = __floats2half2_rn(v.z, v.w);
    __half2* o = (__half2*)&out[4 * (size_t)i];
    o[0] = h0; o[1] = h1;
}

__global__ void cvt_wt_kernel(const float* __restrict__ W, __half* __restrict__ Wt) {
    int i = blockIdx.x * blockDim.x + threadIdx.x;
    if (i >= DIM * DIM) return;
    int n = i >> 8, k = i & 255;
    Wt[i] = __float2half_rn(W[k * DIM + n]);
}

// ---------------- zero accumulators ----------------------------------------
__global__ void zero_kernel() {
    int i = blockIdx.x * blockDim.x + threadIdx.x;
    if (i < N_NODES) {
        g_deg[i] = 0;
        g_attr_sum[2 * i] = 0.f;
        g_attr_sum[2 * i + 1] = 0.f;
    }
}

// ---------------- degree count + scatter-mean of edge_attr by dst ----------
__global__ void edge_stats_kernel(const int* __restrict__ edge_index,
                                  const float* __restrict__ edge_attr) {
    int e = blockIdx.x * blockDim.x + threadIdx.x;
    if (e >= E_EDGES) return;
    int d = edge_index[E_EDGES + e];
    atomicAdd(&g_attr_sum[2 * d],     edge_attr[2 * e]);
    atomicAdd(&g_attr_sum[2 * d + 1], edge_attr[2 * e + 1]);
    atomicAdd(&g_deg[d], 1);
}

// ---------------- 3-phase parallel exclusive scan of degrees ---------------
__global__ __launch_bounds__(SCAN_BLK)
void scan_phase1_kernel() {
    __shared__ int warp_sums[32];
    int tid = threadIdx.x;
    int lane = tid & 31;
    int wid = tid >> 5;
    int idx = blockIdx.x * SCAN_BLK + tid;

    int v = (idx < N_NODES) ? g_deg[idx] : 0;
    int incl = v;
#pragma unroll
    for (int off = 1; off < 32; off <<= 1) {
        int t = __shfl_up_sync(0xffffffffu, incl, off);
        if (lane >= off) incl += t;
    }
    if (lane == 31) warp_sums[wid] = incl;
    __syncthreads();
    if (wid == 0) {
        int w = warp_sums[lane];
        int wi = w;
#pragma unroll
        for (int off = 1; off < 32; off <<= 1) {
            int t = __shfl_up_sync(0xffffffffu, wi, off);
            if (lane >= off) wi += t;
        }
        warp_sums[lane] = wi - w;
        if (lane == 31) g_block_sums[blockIdx.x] = wi;
    }
    __syncthreads();
    if (idx < N_NODES)
        g_scan_tmp[idx] = warp_sums[wid] + incl - v;
}

__global__ void scan_phase2_kernel() {
    int lane = threadIdx.x;
    int v0 = (lane < NBLK_SCAN) ? g_block_sums[lane] : 0;
    int v1 = (lane + 32 < NBLK_SCAN) ? g_block_sums[lane + 32] : 0;

    int i0 = v0;
#pragma unroll
    for (int off = 1; off < 32; off <<= 1) {
        int t = __shfl_up_sync(0xffffffffu, i0, off);
        if (lane >= off) i0 += t;
    }
    int total0 = __shfl_sync(0xffffffffu, i0, 31);

    int i1 = v1;
#pragma unroll
    for (int off = 1; off < 32; off <<= 1) {
        int t = __shfl_up_sync(0xffffffffu, i1, off);
        if (lane >= off) i1 += t;
    }

    if (lane < NBLK_SCAN)      g_block_off[lane]      = i0 - v0;
    if (lane + 32 < NBLK_SCAN) g_block_off[lane + 32] = total0 + i1 - v1;
}

__global__ void scan_phase3_kernel() {
    int i = blockIdx.x * blockDim.x + threadIdx.x;
    if (i >= N_NODES) return;
    int rs = g_scan_tmp[i] + g_block_off[i / SCAN_BLK];
    g_row_start[i] = rs;
    g_fill[i] = rs;
    float c = fmaxf((float)g_deg[i], 1.0f);
    g_loop_attr[2 * i]     = g_attr_sum[2 * i] / c;
    g_loop_attr[2 * i + 1] = g_attr_sum[2 * i + 1] / c;
}

// ---------------- CSR fill (packed 16B records) ------------------------------
__global__ void csr_fill_kernel(const int* __restrict__ edge_index,
                                const float* __restrict__ edge_attr) {
    int e = blockIdx.x * blockDim.x + threadIdx.x;
    if (e >= E_EDGES) return;
    int d = edge_index[E_EDGES + e];
    int pos = atomicAdd(&g_fill[d], 1);
    uint4 r;
    r.x = (unsigned)edge_index[e];
    r.y = __float_as_uint(edge_attr[2 * e]);
    r.z = __float_as_uint(edge_attr[2 * e + 1]);
    r.w = 0;
    g_csr_rec[pos] = r;
}

// ============================================================================
// FP16 tensor-core dual GEMM (unchanged from R10)
// ============================================================================
#define GBM 128
#define GBN 128
#define GBK 32
#define PITCH 40

__device__ __forceinline__ void mma_f16(float4& d, const uint32_t* a, const uint32_t* b) {
    asm volatile(
        "mma.sync.aligned.m16n8k16.row.col.f32.f16.f16.f32 "
        "{%0,%1,%2,%3}, {%4,%5,%6,%7}, {%8,%9}, {%0,%1,%2,%3};"
        : "+f"(d.x), "+f"(d.y), "+f"(d.z), "+f"(d.w)
        : "r"(a[0]), "r"(a[1]), "r"(a[2]), "r"(a[3]), "r"(b[0]), "r"(b[1]));
}

__device__ __forceinline__ void cp_async16(uint32_t smem_dst, const void* gmem_src, int src_bytes) {
    asm volatile("cp.async.cg.shared.global [%0], [%1], 16, %2;"
                 :: "r"(smem_dst), "l"(gmem_src), "r"(src_bytes));
}
__device__ __forceinline__ void cp_commit() { asm volatile("cp.async.commit_group;"); }
template<int NN> __device__ __forceinline__ void cp_wait() {
    asm volatile("cp.async.wait_group %0;" :: "n"(NN));
}

__global__ __launch_bounds__(256)
void gemm_f16_kernel(const __half* __restrict__ A,
                     const __half* __restrict__ Bl,
                     const __half* __restrict__ Br,
                     int M) {
    __shared__ __half As[2][GBM * PITCH];
    __shared__ __half Bs[2][GBN * PITCH];

    const int tid  = threadIdx.x;
    const int wid  = tid >> 5;
    const int lane = tid & 31;
    const int g    = lane >> 2;
    const int tg   = lane & 3;

    const int warpM = wid & 1;
    const int warpN = wid >> 1;

    const int bm = blockIdx.x * GBM;
    const int bn = blockIdx.y * GBN;
    const __half* B = (blockIdx.z == 0) ? Bl : Br;
    __half* Cout = (blockIdx.z == 0) ? g_xl_h : g_xr_h;

    float4 acc[4][4];
#pragma unroll
    for (int i = 0; i < 4; i++)
#pragma unroll
        for (int j = 0; j < 4; j++) acc[i][j] = make_float4(0.f, 0.f, 0.f, 0.f);

    auto load_tiles = [&](int kt, int st) {
#pragma unroll
        for (int r = 0; r < 2; r++) {
            int f = tid + r * 256;
            int row = f >> 2, c = f & 3;
            const __half* srcA = (bm + row < M) ? &A[(size_t)(bm + row) * DIM + kt + c * 8]
                                                : &A[(size_t)bm * DIM + kt + c * 8];
            uint32_t dstA = (uint32_t)__cvta_generic_to_shared(&As[st][row * PITCH + c * 8]);
            cp_async16(dstA, srcA, (bm + row < M) ? 16 : 0);

            const __half* srcB = &B[(size_t)(bn + row) * DIM + kt + c * 8];
            uint32_t dstB = (uint32_t)__cvta_generic_to_shared(&Bs[st][row * PITCH + c * 8]);
            cp_async16(dstB, srcB, 16);
        }
        cp_commit();
    };

    const int NITER = DIM / GBK;
    load_tiles(0, 0);

    for (int it = 0; it < NITER; it++) {
        int st = it & 1;
        if (it + 1 < NITER) {
            load_tiles((it + 1) * GBK, st ^ 1);
            cp_wait<1>();
        } else {
            cp_wait<0>();
        }
        __syncthreads();

        const __half* as = As[st];
        const __half* bs = Bs[st];
#pragma unroll
        for (int ks = 0; ks < 2; ks++) {
            int k0 = ks * 16;
            uint32_t af[4][4];
#pragma unroll
            for (int mt = 0; mt < 4; mt++) {
                int m0 = warpM * 64 + mt * 16;
                int base = (m0 + g) * PITCH + k0 + 2 * tg;
                af[mt][0] = *(const uint32_t*)&as[base];
                af[mt][1] = *(const uint32_t*)&as[base + 8 * PITCH];
                af[mt][2] = *(const uint32_t*)&as[base + 8];
                af[mt][3] = *(const uint32_t*)&as[base + 8 * PITCH + 8];
            }
            uint32_t bf[4][2];
#pragma unroll
            for (int nt = 0; nt < 4; nt++) {
                int n0 = warpN * 32 + nt * 8 + g;
                int bbase = n0 * PITCH + k0 + 2 * tg;
                bf[nt][0] = *(const uint32_t*)&bs[bbase];
                bf[nt][1] = *(const uint32_t*)&bs[bbase + 8];
            }
#pragma unroll
            for (int mt = 0; mt < 4; mt++)
#pragma unroll
                for (int nt = 0; nt < 4; nt++)
                    mma_f16(acc[mt][nt], af[mt], bf[nt]);
        }
        __syncthreads();
    }

#pragma unroll
    for (int mt = 0; mt < 4; mt++) {
        int r0 = bm + warpM * 64 + mt * 16 + g;
        int r1 = r0 + 8;
#pragma unroll
        for (int nt = 0; nt < 4; nt++) {
            int col = bn + warpN * 32 + nt * 8 + tg * 2;
            if (r0 < M)
                *(__half2*)&Cout[(size_t)r0 * DIM + col] = __floats2half2_rn(acc[mt][nt].x, acc[mt][nt].y);
            if (r1 < M)
                *(__half2*)&Cout[(size_t)r1 * DIM + col] = __floats2half2_rn(acc[mt][nt].z, acc[mt][nt].w);
        }
    }
}

// ============================================================================
// node-centric fused pass v3: warp per node, 2-edge interleaved pipeline.
// CSR records prefetched 2 pairs ahead; xl gathers 1 pair ahead. The two
// edges' shfl/exp chains interleave to fill in-order issue stalls.
// ============================================================================
__global__ __launch_bounds__(256)
void node_fused_kernel(const float* __restrict__ W_e,
                       const float* __restrict__ att,
                       const float* __restrict__ bias,
                       float* __restrict__ out) {
    __shared__ float sWe0[DIM];
    __shared__ float sWe1[DIM];
    __shared__ float sAtt[DIM];
    __shared__ float sBias[DIM];
    for (int i = threadIdx.x; i < DIM; i += blockDim.x) {
        sWe0[i] = W_e[i];
        sWe1[i] = W_e[DIM + i];
        sAtt[i] = att[i];
        sBias[i] = bias[i];
    }
    __syncthreads();

    int warp = (int)((blockIdx.x * (size_t)blockDim.x + threadIdx.x) >> 5);
    int lane = threadIdx.x & 31;
    if (warp >= N_NODES) return;
    int n = warp;
    int ch0 = lane * 8;

    float xr[8];
    {
        uint4 rv = *(const uint4*)&g_xr_h[(size_t)n * DIM + ch0];
        const __half2* rh = (const __half2*)&rv;
#pragma unroll
        for (int j = 0; j < 4; j++) {
            float2 f = __half22float2(rh[j]);
            xr[2 * j] = f.x; xr[2 * j + 1] = f.y;
        }
    }

    float we0[8], we1[8], av[8];
#pragma unroll
    for (int j = 0; j < 8; j++) {
        we0[j] = sWe0[ch0 + j];
        we1[j] = sWe1[ch0 + j];
        av[j]  = sAtt[ch0 + j];
    }

    float acc[8] = {0.f, 0.f, 0.f, 0.f, 0.f, 0.f, 0.f, 0.f};
    float denom = 0.f;

    int row = g_row_start[n];
    int deg = g_deg[n];

    // ---- self loop ----
    {
        float ea0 = g_loop_attr[2 * n];
        float ea1 = g_loop_attr[2 * n + 1];
        uint4 lv = *(const uint4*)&g_xl_h[(size_t)n * DIM + ch0];
        const __half2* lh = (const __half2*)&lv;
        float xl[8];
#pragma unroll
        for (int j = 0; j < 4; j++) {
            float2 f = __half22float2(lh[j]);
            xl[2 * j] = f.x; xl[2 * j + 1] = f.y;
        }
        float p = 0.f;
#pragma unroll
        for (int j = 0; j < 8; j++) {
            float m = xl[j] + xr[j] + ea0 * we0[j] + ea1 * we1[j];
            m = (m > 0.f) ? m : 0.2f * m;
            p += m * av[j];
        }
        p += __shfl_xor_sync(0xffffffffu, p, 1);
        p += __shfl_xor_sync(0xffffffffu, p, 2);
        float ex = __expf(p);
        denom += ex;
#pragma unroll
        for (int j = 0; j < 8; j++) acc[j] += ex * xl[j];
    }

    // ---- neighbor edges: 2-edge pipeline ----
    if (deg > 0) {
        // pair 0 records + gathers
        uint4 rc0 = g_csr_rec[row];
        uint4 rc1 = (deg > 1) ? g_csr_rec[row + 1] : rc0;
        // pair 1 records (prefetch)
        uint4 rn0 = rc0, rn1 = rc0;
        if (deg > 2) {
            rn0 = g_csr_rec[row + 2];
            rn1 = (deg > 3) ? g_csr_rec[row + 3] : rn0;
        }
        uint4 gc0 = *(const uint4*)&g_xl_h[(size_t)rc0.x * DIM + ch0];
        uint4 gc1 = *(const uint4*)&g_xl_h[(size_t)rc1.x * DIM + ch0];

        for (int i = 0; i < deg; i += 2) {
            // prefetch records for pair i+4
            uint4 rf0 = rn0, rf1 = rn1;
            if (i + 4 < deg) {
                rf0 = g_csr_rec[row + i + 4];
                rf1 = (i + 5 < deg) ? g_csr_rec[row + i + 5] : rf0;
            }
            // prefetch gathers for pair i+2 (records ready from last iter)
            uint4 gn0 = gc0, gn1 = gc1;
            if (i + 2 < deg) {
                gn0 = *(const uint4*)&g_xl_h[(size_t)rn0.x * DIM + ch0];
                gn1 = *(const uint4*)&g_xl_h[(size_t)rn1.x * DIM + ch0];
            }

            bool hasb = (i + 1 < deg);
            float ea0a = __uint_as_float(rc0.y), ea1a = __uint_as_float(rc0.z);
            float ea0b = __uint_as_float(rc1.y), ea1b = __uint_as_float(rc1.z);

            float xla[8], xlb[8];
            {
                const __half2* la = (const __half2*)&gc0;
                const __half2* lb = (const __half2*)&gc1;
#pragma unroll
                for (int q = 0; q < 4; q++) {
                    float2 fa = __half22float2(la[q]);
                    float2 fb = __half22float2(lb[q]);
                    xla[2 * q] = fa.x; xla[2 * q + 1] = fa.y;
                    xlb[2 * q] = fb.x; xlb[2 * q + 1] = fb.y;
                }
            }
            float pa = 0.f, pb = 0.f;
#pragma unroll
            for (int q = 0; q < 8; q++) {
                float ma = xla[q] + xr[q] + ea0a * we0[q] + ea1a * we1[q];
                float mb = xlb[q] + xr[q] + ea0b * we0[q] + ea1b * we1[q];
                ma = (ma > 0.f) ? ma : 0.2f * ma;
                mb = (mb > 0.f) ? mb : 0.2f * mb;
                pa += ma * av[q];
                pb += mb * av[q];
            }
            // interleaved reductions: b's chain fills a's stalls
            pa += __shfl_xor_sync(0xffffffffu, pa, 1);
            pb += __shfl_xor_sync(0xffffffffu, pb, 1);
            pa += __shfl_xor_sync(0xffffffffu, pa, 2);
            pb += __shfl_xor_sync(0xffffffffu, pb, 2);

            float exa = __expf(pa);
            float exb = hasb ? __expf(pb) : 0.f;
            denom += exa;
            denom += exb;
#pragma unroll
            for (int q = 0; q < 8; q++) acc[q] += exa * xla[q];
#pragma unroll
            for (int q = 0; q < 8; q++) acc[q] += exb * xlb[q];

            rc0 = rn0; rc1 = rn1; rn0 = rf0; rn1 = rf1;
            gc0 = gn0; gc1 = gn1;
        }
    }

    float inv = 1.0f / denom;
    float4 o0 = make_float4(acc[0] * inv + sBias[ch0 + 0], acc[1] * inv + sBias[ch0 + 1],
                            acc[2] * inv + sBias[ch0 + 2], acc[3] * inv + sBias[ch0 + 3]);
    float4 o1 = make_float4(acc[4] * inv + sBias[ch0 + 4], acc[5] * inv + sBias[ch0 + 5],
                            acc[6] * inv + sBias[ch0 + 6], acc[7] * inv + sBias[ch0 + 7]);
    *(float4*)&out[(size_t)n * DIM + ch0]     = o0;
    *(float4*)&out[(size_t)n * DIM + ch0 + 4] = o1;
}

// ---------------- launch: fork GEMM branch onto a side stream ---------------
extern "C" void kernel_launch(void* const* d_in, const int* in_sizes, int n_in,
                              void* d_out, int out_size) {
    const float* x          = (const float*)d_in[0];
    const int*   edge_index = (const int*)  d_in[1];
    const float* edge_attr  = (const float*)d_in[2];
    const float* W_l        = (const float*)d_in[3];
    const float* W_r        = (const float*)d_in[4];
    const float* W_e        = (const float*)d_in[5];
    const float* att        = (const float*)d_in[6];
    const float* bias       = (const float*)d_in[7];
    float* out = (float*)d_out;

    cudaStream_t s1;
    cudaStreamCreateWithFlags(&s1, cudaStreamNonBlocking);
    cudaEvent_t ev_fork, ev_gemm;
    cudaEventCreateWithFlags(&ev_fork, cudaEventDisableTiming);
    cudaEventCreateWithFlags(&ev_gemm, cudaEventDisableTiming);

    // fork
    cudaEventRecord(ev_fork, 0);
    cudaStreamWaitEvent(s1, ev_fork, 0);

    // branch A (side stream): fp16 convert + dual GEMM
    __half* x_h;  cudaGetSymbolAddress((void**)&x_h,  g_x_h);
    __half* wl_h; cudaGetSymbolAddress((void**)&wl_h, g_wl_ht);
    __half* wr_h; cudaGetSymbolAddress((void**)&wr_h, g_wr_ht);
    int n4_x = N_NODES * DIM / 4;
    cvt_half_kernel<<<(n4_x + 255) / 256, 256, 0, s1>>>((const float4*)x, x_h, n4_x);
    cvt_wt_kernel<<<(DIM * DIM + 255) / 256, 256, 0, s1>>>(W_l, wl_h);
    cvt_wt_kernel<<<(DIM * DIM + 255) / 256, 256, 0, s1>>>(W_r, wr_h);
    dim3 ggrid((N_NODES + GBM - 1) / GBM, DIM / GBN, 2);
    gemm_f16_kernel<<<ggrid, 256, 0, s1>>>(x_h, wl_h, wr_h, N_NODES);
    cudaEventRecord(ev_gemm, s1);

    // branch B (capture stream): CSR build
    zero_kernel<<<(N_NODES + 255) / 256, 256>>>();
    edge_stats_kernel<<<(E_EDGES + 255) / 256, 256>>>(edge_index, edge_attr);
    scan_phase1_kernel<<<NBLK_SCAN, SCAN_BLK>>>();
    scan_phase2_kernel<<<1, 32>>>();
    scan_phase3_kernel<<<(N_NODES + 255) / 256, 256>>>();
    csr_fill_kernel<<<(E_EDGES + 255) / 256, 256>>>(edge_index, edge_attr);

    // join
    cudaStreamWaitEvent(0, ev_gemm, 0);

    int nblk = (N_NODES + 7) / 8;   // 8 warps per block
    node_fused_kernel<<<nblk, 256>>>(W_e, att, bias, out);
}

// round 12
// speedup vs baseline: 1.0344x; 1.0344x over previous
#include <cuda_runtime.h>
#include <cuda_fp16.h>
#include <cuda_bf16.h>
#include <cstdint>

#define N_NODES 50000
#define E_EDGES 800000
#define DIM     256
#define NHEAD   8
#define SCAN_BLK 1024
#define NBLK_SCAN ((N_NODES + SCAN_BLK - 1) / SCAN_BLK)   // 49

// ---------------- device scratch (allocation-free rule: use globals) -------
__device__ float  g_attr_sum[N_NODES * 2];
__device__ int    g_deg[N_NODES];
__device__ float  g_loop_attr[N_NODES * 2];
__device__ __half g_xl_h[(size_t)N_NODES * DIM];   // x @ W_l (fp16)
__device__ __half g_xr_h[(size_t)N_NODES * DIM];   // x @ W_r (fp16)
__device__ int    g_row_start[N_NODES];
__device__ int    g_fill[N_NODES];
__device__ uint4  g_csr_rec[E_EDGES];              // {src, ea0, ea1, 0} packed 16B
__device__ int    g_scan_tmp[N_NODES];
__device__ int    g_block_sums[64];
__device__ int    g_block_off[64];
__device__ __half g_x_h[(size_t)N_NODES * DIM];    // x in fp16
__device__ __half g_wl_ht[DIM * DIM];              // W_l^T in fp16 [n][k]
__device__ __half g_wr_ht[DIM * DIM];              // W_r^T in fp16 [n][k]

// ---------------- fp32 -> fp16 conversion kernels ---------------------------
__global__ void cvt_half_kernel(const float4* __restrict__ in, __half* __restrict__ out, int n4) {
    int i = blockIdx.x * blockDim.x + threadIdx.x;
    if (i >= n4) return;
    float4 v = in[i];
    __half2 h0 = __floats2half2_rn(v.x, v.y);
    __half2 h1 = __floats2half2_rn(v.z, v.w);
    __half2* o = (__half2*)&out[4 * (size_t)i];
    o[0] = h0; o[1] = h1;
}

__global__ void cvt_wt_kernel(const float* __restrict__ W, __half* __restrict__ Wt) {
    int i = blockIdx.x * blockDim.x + threadIdx.x;
    if (i >= DIM * DIM) return;
    int n = i >> 8, k = i & 255;
    Wt[i] = __float2half_rn(W[k * DIM + n]);
}

// ---------------- zero accumulators ----------------------------------------
__global__ void zero_kernel() {
    int i = blockIdx.x * blockDim.x + threadIdx.x;
    if (i < N_NODES) {
        g_deg[i] = 0;
        g_attr_sum[2 * i] = 0.f;
        g_attr_sum[2 * i + 1] = 0.f;
    }
}

// ---------------- degree count + scatter-mean of edge_attr by dst ----------
__global__ void edge_stats_kernel(const int* __restrict__ edge_index,
                                  const float* __restrict__ edge_attr) {
    int e = blockIdx.x * blockDim.x + threadIdx.x;
    if (e >= E_EDGES) return;
    int d = edge_index[E_EDGES + e];
    atomicAdd(&g_attr_sum[2 * d],     edge_attr[2 * e]);
    atomicAdd(&g_attr_sum[2 * d + 1], edge_attr[2 * e + 1]);
    atomicAdd(&g_deg[d], 1);
}

// ---------------- 3-phase parallel exclusive scan of degrees ---------------
__global__ __launch_bounds__(SCAN_BLK)
void scan_phase1_kernel() {
    __shared__ int warp_sums[32];
    int tid = threadIdx.x;
    int lane = tid & 31;
    int wid = tid >> 5;
    int idx = blockIdx.x * SCAN_BLK + tid;

    int v = (idx < N_NODES) ? g_deg[idx] : 0;
    int incl = v;
#pragma unroll
    for (int off = 1; off < 32; off <<= 1) {
        int t = __shfl_up_sync(0xffffffffu, incl, off);
        if (lane >= off) incl += t;
    }
    if (lane == 31) warp_sums[wid] = incl;
    __syncthreads();
    if (wid == 0) {
        int w = warp_sums[lane];
        int wi = w;
#pragma unroll
        for (int off = 1; off < 32; off <<= 1) {
            int t = __shfl_up_sync(0xffffffffu, wi, off);
            if (lane >= off) wi += t;
        }
        warp_sums[lane] = wi - w;
        if (lane == 31) g_block_sums[blockIdx.x] = wi;
    }
    __syncthreads();
    if (idx < N_NODES)
        g_scan_tmp[idx] = warp_sums[wid] + incl - v;
}

__global__ void scan_phase2_kernel() {
    int lane = threadIdx.x;
    int v0 = (lane < NBLK_SCAN) ? g_block_sums[lane] : 0;
    int v1 = (lane + 32 < NBLK_SCAN) ? g_block_sums[lane + 32] : 0;

    int i0 = v0;
#pragma unroll
    for (int off = 1; off < 32; off <<= 1) {
        int t = __shfl_up_sync(0xffffffffu, i0, off);
        if (lane >= off) i0 += t;
    }
    int total0 = __shfl_sync(0xffffffffu, i0, 31);

    int i1 = v1;
#pragma unroll
    for (int off = 1; off < 32; off <<= 1) {
        int t = __shfl_up_sync(0xffffffffu, i1, off);
        if (lane >= off) i1 += t;
    }

    if (lane < NBLK_SCAN)      g_block_off[lane]      = i0 - v0;
    if (lane + 32 < NBLK_SCAN) g_block_off[lane + 32] = total0 + i1 - v1;
}

__global__ void scan_phase3_kernel() {
    int i = blockIdx.x * blockDim.x + threadIdx.x;
    if (i >= N_NODES) return;
    int rs = g_scan_tmp[i] + g_block_off[i / SCAN_BLK];
    g_row_start[i] = rs;
    g_fill[i] = rs;
    float c = fmaxf((float)g_deg[i], 1.0f);
    g_loop_attr[2 * i]     = g_attr_sum[2 * i] / c;
    g_loop_attr[2 * i + 1] = g_attr_sum[2 * i + 1] / c;
}

// ---------------- CSR fill (packed 16B records) ------------------------------
__global__ void csr_fill_kernel(const int* __restrict__ edge_index,
                                const float* __restrict__ edge_attr) {
    int e = blockIdx.x * blockDim.x + threadIdx.x;
    if (e >= E_EDGES) return;
    int d = edge_index[E_EDGES + e];
    int pos = atomicAdd(&g_fill[d], 1);
    uint4 r;
    r.x = (unsigned)edge_index[e];
    r.y = __float_as_uint(edge_attr[2 * e]);
    r.z = __float_as_uint(edge_attr[2 * e + 1]);
    r.w = 0;
    g_csr_rec[pos] = r;
}

// ============================================================================
// FP16 tensor-core dual GEMM (unchanged from R10)
// ============================================================================
#define GBM 128
#define GBN 128
#define GBK 32
#define PITCH 40

__device__ __forceinline__ void mma_f16(float4& d, const uint32_t* a, const uint32_t* b) {
    asm volatile(
        "mma.sync.aligned.m16n8k16.row.col.f32.f16.f16.f32 "
        "{%0,%1,%2,%3}, {%4,%5,%6,%7}, {%8,%9}, {%0,%1,%2,%3};"
        : "+f"(d.x), "+f"(d.y), "+f"(d.z), "+f"(d.w)
        : "r"(a[0]), "r"(a[1]), "r"(a[2]), "r"(a[3]), "r"(b[0]), "r"(b[1]));
}

__device__ __forceinline__ void cp_async16(uint32_t smem_dst, const void* gmem_src, int src_bytes) {
    asm volatile("cp.async.cg.shared.global [%0], [%1], 16, %2;"
                 :: "r"(smem_dst), "l"(gmem_src), "r"(src_bytes));
}
__device__ __forceinline__ void cp_commit() { asm volatile("cp.async.commit_group;"); }
template<int NN> __device__ __forceinline__ void cp_wait() {
    asm volatile("cp.async.wait_group %0;" :: "n"(NN));
}

__global__ __launch_bounds__(256)
void gemm_f16_kernel(const __half* __restrict__ A,
                     const __half* __restrict__ Bl,
                     const __half* __restrict__ Br,
                     int M) {
    __shared__ __half As[2][GBM * PITCH];
    __shared__ __half Bs[2][GBN * PITCH];

    const int tid  = threadIdx.x;
    const int wid  = tid >> 5;
    const int lane = tid & 31;
    const int g    = lane >> 2;
    const int tg   = lane & 3;

    const int warpM = wid & 1;
    const int warpN = wid >> 1;

    const int bm = blockIdx.x * GBM;
    const int bn = blockIdx.y * GBN;
    const __half* B = (blockIdx.z == 0) ? Bl : Br;
    __half* Cout = (blockIdx.z == 0) ? g_xl_h : g_xr_h;

    float4 acc[4][4];
#pragma unroll
    for (int i = 0; i < 4; i++)
#pragma unroll
        for (int j = 0; j < 4; j++) acc[i][j] = make_float4(0.f, 0.f, 0.f, 0.f);

    auto load_tiles = [&](int kt, int st) {
#pragma unroll
        for (int r = 0; r < 2; r++) {
            int f = tid + r * 256;
            int row = f >> 2, c = f & 3;
            const __half* srcA = (bm + row < M) ? &A[(size_t)(bm + row) * DIM + kt + c * 8]
                                                : &A[(size_t)bm * DIM + kt + c * 8];
            uint32_t dstA = (uint32_t)__cvta_generic_to_shared(&As[st][row * PITCH + c * 8]);
            cp_async16(dstA, srcA, (bm + row < M) ? 16 : 0);

            const __half* srcB = &B[(size_t)(bn + row) * DIM + kt + c * 8];
            uint32_t dstB = (uint32_t)__cvta_generic_to_shared(&Bs[st][row * PITCH + c * 8]);
            cp_async16(dstB, srcB, 16);
        }
        cp_commit();
    };

    const int NITER = DIM / GBK;
    load_tiles(0, 0);

    for (int it = 0; it < NITER; it++) {
        int st = it & 1;
        if (it + 1 < NITER) {
            load_tiles((it + 1) * GBK, st ^ 1);
            cp_wait<1>();
        } else {
            cp_wait<0>();
        }
        __syncthreads();

        const __half* as = As[st];
        const __half* bs = Bs[st];
#pragma unroll
        for (int ks = 0; ks < 2; ks++) {
            int k0 = ks * 16;
            uint32_t af[4][4];
#pragma unroll
            for (int mt = 0; mt < 4; mt++) {
                int m0 = warpM * 64 + mt * 16;
                int base = (m0 + g) * PITCH + k0 + 2 * tg;
                af[mt][0] = *(const uint32_t*)&as[base];
                af[mt][1] = *(const uint32_t*)&as[base + 8 * PITCH];
                af[mt][2] = *(const uint32_t*)&as[base + 8];
                af[mt][3] = *(const uint32_t*)&as[base + 8 * PITCH + 8];
            }
            uint32_t bf[4][2];
#pragma unroll
            for (int nt = 0; nt < 4; nt++) {
                int n0 = warpN * 32 + nt * 8 + g;
                int bbase = n0 * PITCH + k0 + 2 * tg;
                bf[nt][0] = *(const uint32_t*)&bs[bbase];
                bf[nt][1] = *(const uint32_t*)&bs[bbase + 8];
            }
#pragma unroll
            for (int mt = 0; mt < 4; mt++)
#pragma unroll
                for (int nt = 0; nt < 4; nt++)
                    mma_f16(acc[mt][nt], af[mt], bf[nt]);
        }
        __syncthreads();
    }

#pragma unroll
    for (int mt = 0; mt < 4; mt++) {
        int r0 = bm + warpM * 64 + mt * 16 + g;
        int r1 = r0 + 8;
#pragma unroll
        for (int nt = 0; nt < 4; nt++) {
            int col = bn + warpN * 32 + nt * 8 + tg * 2;
            if (r0 < M)
                *(__half2*)&Cout[(size_t)r0 * DIM + col] = __floats2half2_rn(acc[mt][nt].x, acc[mt][nt].y);
            if (r1 < M)
                *(__half2*)&Cout[(size_t)r1 * DIM + col] = __floats2half2_rn(acc[mt][nt].z, acc[mt][nt].w);
        }
    }
}

// ============================================================================
// node-centric fused pass v4: TWO warps per node (head-parallel halves).
// Warp-half wh covers channels [128*wh, 128*wh+128) = 4 heads. Lane owns 4
// channels (uint2 gather, 8B). Score reduced over 8-lane groups (3 shfls).
// Depth-1 prefetch (the only structure that has worked). No atomics.
// ============================================================================
__global__ __launch_bounds__(256)
void node_fused_kernel(const float* __restrict__ W_e,
                       const float* __restrict__ att,
                       const float* __restrict__ bias,
                       float* __restrict__ out) {
    __shared__ float sWe0[DIM];
    __shared__ float sWe1[DIM];
    __shared__ float sAtt[DIM];
    __shared__ float sBias[DIM];
    for (int i = threadIdx.x; i < DIM; i += blockDim.x) {
        sWe0[i] = W_e[i];
        sWe1[i] = W_e[DIM + i];
        sAtt[i] = att[i];
        sBias[i] = bias[i];
    }
    __syncthreads();

    int gw = (int)((blockIdx.x * (size_t)blockDim.x + threadIdx.x) >> 5);
    int lane = threadIdx.x & 31;
    int n  = gw >> 1;          // node
    int wh = gw & 1;           // which half of the channels
    if (n >= N_NODES) return;
    int ch0 = wh * 128 + lane * 4;

    // dst projection: 4 halves = uint2
    float xr[4];
    {
        uint2 rv = *(const uint2*)&g_xr_h[(size_t)n * DIM + ch0];
        float2 f0 = __half22float2(*(const __half2*)&rv.x);
        float2 f1 = __half22float2(*(const __half2*)&rv.y);
        xr[0] = f0.x; xr[1] = f0.y; xr[2] = f1.x; xr[3] = f1.y;
    }

    float we0[4], we1[4], av[4];
#pragma unroll
    for (int j = 0; j < 4; j++) {
        we0[j] = sWe0[ch0 + j];
        we1[j] = sWe1[ch0 + j];
        av[j]  = sAtt[ch0 + j];
    }

    float acc[4] = {0.f, 0.f, 0.f, 0.f};
    float denom = 0.f;

    int row = g_row_start[n];
    int deg = g_deg[n];

    // iteration 0 = self loop; prefetch edge operands depth-1.
    float ea0_cur = g_loop_attr[2 * n];
    float ea1_cur = g_loop_attr[2 * n + 1];
    uint2 lv_cur  = *(const uint2*)&g_xl_h[(size_t)n * DIM + ch0];

    for (int i = 0; i <= deg; i++) {
        float ea0_nxt = 0.f, ea1_nxt = 0.f; uint2 lv_nxt;
        if (i < deg) {
            uint4 rec = g_csr_rec[row + i];
            ea0_nxt = __uint_as_float(rec.y);
            ea1_nxt = __uint_as_float(rec.z);
            lv_nxt = *(const uint2*)&g_xl_h[(size_t)rec.x * DIM + ch0];
        }

        float xl[4];
        {
            float2 f0 = __half22float2(*(const __half2*)&lv_cur.x);
            float2 f1 = __half22float2(*(const __half2*)&lv_cur.y);
            xl[0] = f0.x; xl[1] = f0.y; xl[2] = f1.x; xl[3] = f1.y;
        }
        float p = 0.f;
#pragma unroll
        for (int j = 0; j < 4; j++) {
            float m = xl[j] + xr[j] + ea0_cur * we0[j] + ea1_cur * we1[j];
            m = (m > 0.f) ? m : 0.2f * m;       // leaky relu
            p += m * av[j];
        }
        // reduce over the 8-lane group sharing this head
        p += __shfl_xor_sync(0xffffffffu, p, 1);
        p += __shfl_xor_sync(0xffffffffu, p, 2);
        p += __shfl_xor_sync(0xffffffffu, p, 4);

        float ex = __expf(p);
        denom += ex;
#pragma unroll
        for (int j = 0; j < 4; j++) acc[j] += ex * xl[j];

        ea0_cur = ea0_nxt; ea1_cur = ea1_nxt; lv_cur = lv_nxt;
    }

    float inv = 1.0f / denom;
    float4 o = make_float4(acc[0] * inv + sBias[ch0 + 0], acc[1] * inv + sBias[ch0 + 1],
                           acc[2] * inv + sBias[ch0 + 2], acc[3] * inv + sBias[ch0 + 3]);
    *(float4*)&out[(size_t)n * DIM + ch0] = o;
}

// ---------------- launch: fork GEMM branch onto a side stream ---------------
extern "C" void kernel_launch(void* const* d_in, const int* in_sizes, int n_in,
                              void* d_out, int out_size) {
    const float* x          = (const float*)d_in[0];
    const int*   edge_index = (const int*)  d_in[1];
    const float* edge_attr  = (const float*)d_in[2];
    const float* W_l        = (const float*)d_in[3];
    const float* W_r        = (const float*)d_in[4];
    const float* W_e        = (const float*)d_in[5];
    const float* att        = (const float*)d_in[6];
    const float* bias       = (const float*)d_in[7];
    float* out = (float*)d_out;

    cudaStream_t s1;
    cudaStreamCreateWithFlags(&s1, cudaStreamNonBlocking);
    cudaEvent_t ev_fork, ev_gemm;
    cudaEventCreateWithFlags(&ev_fork, cudaEventDisableTiming);
    cudaEventCreateWithFlags(&ev_gemm, cudaEventDisableTiming);

    // fork
    cudaEventRecord(ev_fork, 0);
    cudaStreamWaitEvent(s1, ev_fork, 0);

    // branch A (side stream): fp16 convert + dual GEMM
    __half* x_h;  cudaGetSymbolAddress((void**)&x_h,  g_x_h);
    __half* wl_h; cudaGetSymbolAddress((void**)&wl_h, g_wl_ht);
    __half* wr_h; cudaGetSymbolAddress((void**)&wr_h, g_wr_ht);
    int n4_x = N_NODES * DIM / 4;
    cvt_half_kernel<<<(n4_x + 255) / 256, 256, 0, s1>>>((const float4*)x, x_h, n4_x);
    cvt_wt_kernel<<<(DIM * DIM + 255) / 256, 256, 0, s1>>>(W_l, wl_h);
    cvt_wt_kernel<<<(DIM * DIM + 255) / 256, 256, 0, s1>>>(W_r, wr_h);
    dim3 ggrid((N_NODES + GBM - 1) / GBM, DIM / GBN, 2);
    gemm_f16_kernel<<<ggrid, 256, 0, s1>>>(x_h, wl_h, wr_h, N_NODES);
    cudaEventRecord(ev_gemm, s1);

    // branch B (capture stream): CSR build
    zero_kernel<<<(N_NODES + 255) / 256, 256>>>();
    edge_stats_kernel<<<(E_EDGES + 255) / 256, 256>>>(edge_index, edge_attr);
    scan_phase1_kernel<<<NBLK_SCAN, SCAN_BLK>>>();
    scan_phase2_kernel<<<1, 32>>>();
    scan_phase3_kernel<<<(N_NODES + 255) / 256, 256>>>();
    csr_fill_kernel<<<(E_EDGES + 255) / 256, 256>>>(edge_index, edge_attr);

    // join
    cudaStreamWaitEvent(0, ev_gemm, 0);

    // two warps per node
    int nwarps = 2 * N_NODES;
    int nblk = (nwarps + 7) / 8;
    node_fused_kernel<<<nblk, 256>>>(W_e, att, bias, out);
}

// round 13
// speedup vs baseline: 1.1723x; 1.1333x over previous
#include <cuda_runtime.h>
#include <cuda_fp16.h>
#include <cuda_bf16.h>
#include <cstdint>

#define N_NODES 50000
#define E_EDGES 800000
#define DIM     256
#define NHEAD   8
#define SCAN_BLK 1024
#define NBLK_SCAN ((N_NODES + SCAN_BLK - 1) / SCAN_BLK)   // 49

// ---------------- device scratch (allocation-free rule: use globals) -------
__device__ int    g_deg[N_NODES];
__device__ __half g_xl_h[(size_t)N_NODES * DIM];   // x @ W_l (fp16)
__device__ __half g_xr_h[(size_t)N_NODES * DIM];   // x @ W_r (fp16)
__device__ int    g_row_start[N_NODES];
__device__ int    g_fill[N_NODES];
__device__ uint4  g_csr_rec[E_EDGES];              // {src, ea0, ea1, 0} packed 16B
__device__ int    g_scan_tmp[N_NODES];
__device__ int    g_block_sums[64];
__device__ int    g_block_off[64];
__device__ __half g_x_h[(size_t)N_NODES * DIM];    // x in fp16
__device__ __half g_wl_ht[DIM * DIM];              // W_l^T in fp16 [n][k]
__device__ __half g_wr_ht[DIM * DIM];              // W_r^T in fp16 [n][k]

// ---------------- fp32 -> fp16 conversion kernels ---------------------------
__global__ void cvt_half_kernel(const float4* __restrict__ in, __half* __restrict__ out, int n4) {
    int i = blockIdx.x * blockDim.x + threadIdx.x;
    if (i >= n4) return;
    float4 v = in[i];
    __half2 h0 = __floats2half2_rn(v.x, v.y);
    __half2 h1 = __floats2half2_rn(v.z, v.w);
    __half2* o = (__half2*)&out[4 * (size_t)i];
    o[0] = h0; o[1] = h1;
}

__global__ void cvt_wt_kernel(const float* __restrict__ W, __half* __restrict__ Wt) {
    int i = blockIdx.x * blockDim.x + threadIdx.x;
    if (i >= DIM * DIM) return;
    int n = i >> 8, k = i & 255;
    Wt[i] = __float2half_rn(W[k * DIM + n]);
}

// ---------------- zero degree ------------------------------------------------
__global__ void zero_kernel() {
    int i = blockIdx.x * blockDim.x + threadIdx.x;
    if (i < N_NODES) g_deg[i] = 0;
}

// ---------------- degree count only (loop_attr folded into node_fused) ------
__global__ void edge_stats_kernel(const int* __restrict__ edge_index) {
    int e = blockIdx.x * blockDim.x + threadIdx.x;
    if (e >= E_EDGES) return;
    atomicAdd(&g_deg[edge_index[E_EDGES + e]], 1);
}

// ---------------- 3-phase parallel exclusive scan of degrees ---------------
__global__ __launch_bounds__(SCAN_BLK)
void scan_phase1_kernel() {
    __shared__ int warp_sums[32];
    int tid = threadIdx.x;
    int lane = tid & 31;
    int wid = tid >> 5;
    int idx = blockIdx.x * SCAN_BLK + tid;

    int v = (idx < N_NODES) ? g_deg[idx] : 0;
    int incl = v;
#pragma unroll
    for (int off = 1; off < 32; off <<= 1) {
        int t = __shfl_up_sync(0xffffffffu, incl, off);
        if (lane >= off) incl += t;
    }
    if (lane == 31) warp_sums[wid] = incl;
    __syncthreads();
    if (wid == 0) {
        int w = warp_sums[lane];
        int wi = w;
#pragma unroll
        for (int off = 1; off < 32; off <<= 1) {
            int t = __shfl_up_sync(0xffffffffu, wi, off);
            if (lane >= off) wi += t;
        }
        warp_sums[lane] = wi - w;
        if (lane == 31) g_block_sums[blockIdx.x] = wi;
    }
    __syncthreads();
    if (idx < N_NODES)
        g_scan_tmp[idx] = warp_sums[wid] + incl - v;
}

__global__ void scan_phase2_kernel() {
    int lane = threadIdx.x;
    int v0 = (lane < NBLK_SCAN) ? g_block_sums[lane] : 0;
    int v1 = (lane + 32 < NBLK_SCAN) ? g_block_sums[lane + 32] : 0;

    int i0 = v0;
#pragma unroll
    for (int off = 1; off < 32; off <<= 1) {
        int t = __shfl_up_sync(0xffffffffu, i0, off);
        if (lane >= off) i0 += t;
    }
    int total0 = __shfl_sync(0xffffffffu, i0, 31);

    int i1 = v1;
#pragma unroll
    for (int off = 1; off < 32; off <<= 1) {
        int t = __shfl_up_sync(0xffffffffu, i1, off);
        if (lane >= off) i1 += t;
    }

    if (lane < NBLK_SCAN)      g_block_off[lane]      = i0 - v0;
    if (lane + 32 < NBLK_SCAN) g_block_off[lane + 32] = total0 + i1 - v1;
}

__global__ void scan_phase3_kernel() {
    int i = blockIdx.x * blockDim.x + threadIdx.x;
    if (i >= N_NODES) return;
    int rs = g_scan_tmp[i] + g_block_off[i / SCAN_BLK];
    g_row_start[i] = rs;
    g_fill[i] = rs;
}

// ---------------- CSR fill (packed 16B records) ------------------------------
__global__ void csr_fill_kernel(const int* __restrict__ edge_index,
                                const float* __restrict__ edge_attr) {
    int e = blockIdx.x * blockDim.x + threadIdx.x;
    if (e >= E_EDGES) return;
    int d = edge_index[E_EDGES + e];
    int pos = atomicAdd(&g_fill[d], 1);
    uint4 r;
    r.x = (unsigned)edge_index[e];
    r.y = __float_as_uint(edge_attr[2 * e]);
    r.z = __float_as_uint(edge_attr[2 * e + 1]);
    r.w = 0;
    g_csr_rec[pos] = r;
}

// ============================================================================
// FP16 tensor-core dual GEMM with ldmatrix fragment loads.
// A = x_h [M][256] half. B = W^T [n][k] half. BM=BN=128, BK=32, PITCH=40
// (conflict-free for 8-row ldmatrix: banks (20r)%32 distinct).
// ============================================================================
#define GBM 128
#define GBN 128
#define GBK 32
#define PITCH 40

__device__ __forceinline__ void mma_f16(float4& d, const uint32_t* a, const uint32_t* b) {
    asm volatile(
        "mma.sync.aligned.m16n8k16.row.col.f32.f16.f16.f32 "
        "{%0,%1,%2,%3}, {%4,%5,%6,%7}, {%8,%9}, {%0,%1,%2,%3};"
        : "+f"(d.x), "+f"(d.y), "+f"(d.z), "+f"(d.w)
        : "r"(a[0]), "r"(a[1]), "r"(a[2]), "r"(a[3]), "r"(b[0]), "r"(b[1]));
}

__device__ __forceinline__ void ldsm_x4(uint32_t& r0, uint32_t& r1, uint32_t& r2, uint32_t& r3,
                                        uint32_t addr) {
    asm volatile("ldmatrix.sync.aligned.m8n8.x4.shared.b16 {%0,%1,%2,%3}, [%4];"
                 : "=r"(r0), "=r"(r1), "=r"(r2), "=r"(r3) : "r"(addr));
}

__device__ __forceinline__ void cp_async16(uint32_t smem_dst, const void* gmem_src, int src_bytes) {
    asm volatile("cp.async.cg.shared.global [%0], [%1], 16, %2;"
                 :: "r"(smem_dst), "l"(gmem_src), "r"(src_bytes));
}
__device__ __forceinline__ void cp_commit() { asm volatile("cp.async.commit_group;"); }
template<int NN> __device__ __forceinline__ void cp_wait() {
    asm volatile("cp.async.wait_group %0;" :: "n"(NN));
}

__global__ __launch_bounds__(256)
void gemm_f16_kernel(const __half* __restrict__ A,
                     const __half* __restrict__ Bl,
                     const __half* __restrict__ Br,
                     int M) {
    __shared__ __half As[2][GBM * PITCH];
    __shared__ __half Bs[2][GBN * PITCH];

    const int tid  = threadIdx.x;
    const int wid  = tid >> 5;
    const int lane = tid & 31;
    const int g    = lane >> 2;
    const int tg   = lane & 3;

    const int warpM = wid & 1;
    const int warpN = wid >> 1;

    const int bm = blockIdx.x * GBM;
    const int bn = blockIdx.y * GBN;
    const __half* B = (blockIdx.z == 0) ? Bl : Br;
    __half* Cout = (blockIdx.z == 0) ? g_xl_h : g_xr_h;

    // ldmatrix per-lane geometry
    // A x4: matrices (rows m0..+7,k0) (m0+8..+15,k0) (m0..+7,k0+8) (m0+8..15,k0+8)
    const int rowA = (lane & 7) + 8 * ((lane >> 3) & 1);
    const int colA = (lane >> 4) * 8;
    // B x4 over an nt-pair: (nt,k0) (nt,k0+8) (nt+1,k0) (nt+1,k0+8)
    const int qb   = lane >> 3;
    const int rowB = (lane & 7) + ((qb >> 1) * 8);   // +8 rows for second nt
    const int colB = (qb & 1) * 8;

    uint32_t asBase[2], bsBase[2];
    asBase[0] = (uint32_t)__cvta_generic_to_shared(&As[0][0]);
    asBase[1] = (uint32_t)__cvta_generic_to_shared(&As[1][0]);
    bsBase[0] = (uint32_t)__cvta_generic_to_shared(&Bs[0][0]);
    bsBase[1] = (uint32_t)__cvta_generic_to_shared(&Bs[1][0]);

    float4 acc[4][4];
#pragma unroll
    for (int i = 0; i < 4; i++)
#pragma unroll
        for (int j = 0; j < 4; j++) acc[i][j] = make_float4(0.f, 0.f, 0.f, 0.f);

    auto load_tiles = [&](int kt, int st) {
#pragma unroll
        for (int r = 0; r < 2; r++) {
            int f = tid + r * 256;
            int row = f >> 2, c = f & 3;
            const __half* srcA = (bm + row < M) ? &A[(size_t)(bm + row) * DIM + kt + c * 8]
                                                : &A[(size_t)bm * DIM + kt + c * 8];
            uint32_t dstA = (uint32_t)__cvta_generic_to_shared(&As[st][row * PITCH + c * 8]);
            cp_async16(dstA, srcA, (bm + row < M) ? 16 : 0);

            const __half* srcB = &B[(size_t)(bn + row) * DIM + kt + c * 8];
            uint32_t dstB = (uint32_t)__cvta_generic_to_shared(&Bs[st][row * PITCH + c * 8]);
            cp_async16(dstB, srcB, 16);
        }
        cp_commit();
    };

    const int NITER = DIM / GBK;
    load_tiles(0, 0);

    for (int it = 0; it < NITER; it++) {
        int st = it & 1;
        if (it + 1 < NITER) {
            load_tiles((it + 1) * GBK, st ^ 1);
            cp_wait<1>();
        } else {
            cp_wait<0>();
        }
        __syncthreads();

#pragma unroll
        for (int ks = 0; ks < 2; ks++) {
            int k0 = ks * 16;
            uint32_t af[4][4];
#pragma unroll
            for (int mt = 0; mt < 4; mt++) {
                int m0 = warpM * 64 + mt * 16;
                uint32_t addr = asBase[st] + 2u * ((m0 + rowA) * PITCH + k0 + colA);
                ldsm_x4(af[mt][0], af[mt][1], af[mt][2], af[mt][3], addr);
            }
            uint32_t bf[4][2];
#pragma unroll
            for (int ntp = 0; ntp < 2; ntp++) {
                int n0 = warpN * 32 + ntp * 16;
                uint32_t addr = bsBase[st] + 2u * ((n0 + rowB) * PITCH + k0 + colB);
                ldsm_x4(bf[2 * ntp][0], bf[2 * ntp][1], bf[2 * ntp + 1][0], bf[2 * ntp + 1][1], addr);
            }
#pragma unroll
            for (int mt = 0; mt < 4; mt++)
#pragma unroll
                for (int nt = 0; nt < 4; nt++)
                    mma_f16(acc[mt][nt], af[mt], bf[nt]);
        }
        __syncthreads();
    }

#pragma unroll
    for (int mt = 0; mt < 4; mt++) {
        int r0 = bm + warpM * 64 + mt * 16 + g;
        int r1 = r0 + 8;
#pragma unroll
        for (int nt = 0; nt < 4; nt++) {
            int col = bn + warpN * 32 + nt * 8 + tg * 2;
            if (r0 < M)
                *(__half2*)&Cout[(size_t)r0 * DIM + col] = __floats2half2_rn(acc[mt][nt].x, acc[mt][nt].y);
            if (r1 < M)
                *(__half2*)&Cout[(size_t)r1 * DIM + col] = __floats2half2_rn(acc[mt][nt].z, acc[mt][nt].w);
        }
    }
}

// ============================================================================
// node-centric fused pass v5: warp per node, depth-1 prefetch (R10 structure).
// loop_attr computed in-register (ea sums over edges), self-loop handled last.
// No atomics.
// ============================================================================
__global__ __launch_bounds__(256)
void node_fused_kernel(const float* __restrict__ W_e,
                       const float* __restrict__ att,
                       const float* __restrict__ bias,
                       float* __restrict__ out) {
    __shared__ float sWe0[DIM];
    __shared__ float sWe1[DIM];
    __shared__ float sAtt[DIM];
    __shared__ float sBias[DIM];
    for (int i = threadIdx.x; i < DIM; i += blockDim.x) {
        sWe0[i] = W_e[i];
        sWe1[i] = W_e[DIM + i];
        sAtt[i] = att[i];
        sBias[i] = bias[i];
    }
    __syncthreads();

    int warp = (int)((blockIdx.x * (size_t)blockDim.x + threadIdx.x) >> 5);
    int lane = threadIdx.x & 31;
    if (warp >= N_NODES) return;
    int n = warp;
    int ch0 = lane * 8;

    float xr[8];
    {
        uint4 rv = *(const uint4*)&g_xr_h[(size_t)n * DIM + ch0];
        const __half2* rh = (const __half2*)&rv;
#pragma unroll
        for (int j = 0; j < 4; j++) {
            float2 f = __half22float2(rh[j]);
            xr[2 * j] = f.x; xr[2 * j + 1] = f.y;
        }
    }

    float we0[8], we1[8], av[8];
#pragma unroll
    for (int j = 0; j < 8; j++) {
        we0[j] = sWe0[ch0 + j];
        we1[j] = sWe1[ch0 + j];
        av[j]  = sAtt[ch0 + j];
    }

    float acc[8] = {0.f, 0.f, 0.f, 0.f, 0.f, 0.f, 0.f, 0.f};
    float denom = 0.f;
    float eas0 = 0.f, eas1 = 0.f;    // running sums of incoming edge_attr

    int row = g_row_start[n];
    int deg = g_deg[n];

    // ---- neighbor edges (depth-1 prefetch) ----
    if (deg > 0) {
        uint4 rec = g_csr_rec[row];
        float ea0_cur = __uint_as_float(rec.y);
        float ea1_cur = __uint_as_float(rec.z);
        uint4 lv_cur  = *(const uint4*)&g_xl_h[(size_t)rec.x * DIM + ch0];

        for (int i = 0; i < deg; i++) {
            float ea0_nxt = 0.f, ea1_nxt = 0.f; uint4 lv_nxt;
            if (i + 1 < deg) {
                uint4 rn = g_csr_rec[row + i + 1];
                ea0_nxt = __uint_as_float(rn.y);
                ea1_nxt = __uint_as_float(rn.z);
                lv_nxt = *(const uint4*)&g_xl_h[(size_t)rn.x * DIM + ch0];
            }

            float xl[8];
            {
                const __half2* lh = (const __half2*)&lv_cur;
#pragma unroll
                for (int j = 0; j < 4; j++) {
                    float2 f = __half22float2(lh[j]);
                    xl[2 * j] = f.x; xl[2 * j + 1] = f.y;
                }
            }
            float p = 0.f;
#pragma unroll
            for (int j = 0; j < 8; j++) {
                float m = xl[j] + xr[j] + ea0_cur * we0[j] + ea1_cur * we1[j];
                m = (m > 0.f) ? m : 0.2f * m;       // leaky relu
                p += m * av[j];
            }
            p += __shfl_xor_sync(0xffffffffu, p, 1);
            p += __shfl_xor_sync(0xffffffffu, p, 2);

            float ex = __expf(p);
            denom += ex;
            eas0 += ea0_cur;
            eas1 += ea1_cur;
#pragma unroll
            for (int j = 0; j < 8; j++) acc[j] += ex * xl[j];

            ea0_cur = ea0_nxt; ea1_cur = ea1_nxt; lv_cur = lv_nxt;
        }
    }

    // ---- self loop (loop_attr = mean incoming ea) ----
    {
        float invc = 1.0f / fmaxf((float)deg, 1.0f);
        float ea0 = eas0 * invc;
        float ea1 = eas1 * invc;
        uint4 lv = *(const uint4*)&g_xl_h[(size_t)n * DIM + ch0];
        const __half2* lh = (const __half2*)&lv;
        float xl[8];
#pragma unroll
        for (int j = 0; j < 4; j++) {
            float2 f = __half22float2(lh[j]);
            xl[2 * j] = f.x; xl[2 * j + 1] = f.y;
        }
        float p = 0.f;
#pragma unroll
        for (int j = 0; j < 8; j++) {
            float m = xl[j] + xr[j] + ea0 * we0[j] + ea1 * we1[j];
            m = (m > 0.f) ? m : 0.2f * m;
            p += m * av[j];
        }
        p += __shfl_xor_sync(0xffffffffu, p, 1);
        p += __shfl_xor_sync(0xffffffffu, p, 2);
        float ex = __expf(p);
        denom += ex;
#pragma unroll
        for (int j = 0; j < 8; j++) acc[j] += ex * xl[j];
    }

    float inv = 1.0f / denom;
    float4 o0 = make_float4(acc[0] * inv + sBias[ch0 + 0], acc[1] * inv + sBias[ch0 + 1],
                            acc[2] * inv + sBias[ch0 + 2], acc[3] * inv + sBias[ch0 + 3]);
    float4 o1 = make_float4(acc[4] * inv + sBias[ch0 + 4], acc[5] * inv + sBias[ch0 + 5],
                            acc[6] * inv + sBias[ch0 + 6], acc[7] * inv + sBias[ch0 + 7]);
    *(float4*)&out[(size_t)n * DIM + ch0]     = o0;
    *(float4*)&out[(size_t)n * DIM + ch0 + 4] = o1;
}

// ---------------- launch: fork GEMM branch onto a side stream ---------------
extern "C" void kernel_launch(void* const* d_in, const int* in_sizes, int n_in,
                              void* d_out, int out_size) {
    const float* x          = (const float*)d_in[0];
    const int*   edge_index = (const int*)  d_in[1];
    const float* edge_attr  = (const float*)d_in[2];
    const float* W_l        = (const float*)d_in[3];
    const float* W_r        = (const float*)d_in[4];
    const float* W_e        = (const float*)d_in[5];
    const float* att        = (const float*)d_in[6];
    const float* bias       = (const float*)d_in[7];
    float* out = (float*)d_out;

    cudaStream_t s1;
    cudaStreamCreateWithFlags(&s1, cudaStreamNonBlocking);
    cudaEvent_t ev_fork, ev_gemm;
    cudaEventCreateWithFlags(&ev_fork, cudaEventDisableTiming);
    cudaEventCreateWithFlags(&ev_gemm, cudaEventDisableTiming);

    // fork
    cudaEventRecord(ev_fork, 0);
    cudaStreamWaitEvent(s1, ev_fork, 0);

    // branch A (side stream): fp16 convert + dual GEMM
    __half* x_h;  cudaGetSymbolAddress((void**)&x_h,  g_x_h);
    __half* wl_h; cudaGetSymbolAddress((void**)&wl_h, g_wl_ht);
    __half* wr_h; cudaGetSymbolAddress((void**)&wr_h, g_wr_ht);
    int n4_x = N_NODES * DIM / 4;
    cvt_half_kernel<<<(n4_x + 255) / 256, 256, 0, s1>>>((const float4*)x, x_h, n4_x);
    cvt_wt_kernel<<<(DIM * DIM + 255) / 256, 256, 0, s1>>>(W_l, wl_h);
    cvt_wt_kernel<<<(DIM * DIM + 255) / 256, 256, 0, s1>>>(W_r, wr_h);
    dim3 ggrid((N_NODES + GBM - 1) / GBM, DIM / GBN, 2);
    gemm_f16_kernel<<<ggrid, 256, 0, s1>>>(x_h, wl_h, wr_h, N_NODES);
    cudaEventRecord(ev_gemm, s1);

    // branch B (capture stream): CSR build
    zero_kernel<<<(N_NODES + 255) / 256, 256>>>();
    edge_stats_kernel<<<(E_EDGES + 511) / 512, 512>>>(edge_index);
    scan_phase1_kernel<<<NBLK_SCAN, SCAN_BLK>>>();
    scan_phase2_kernel<<<1, 32>>>();
    scan_phase3_kernel<<<(N_NODES + 255) / 256, 256>>>();
    csr_fill_kernel<<<(E_EDGES + 255) / 256, 256>>>(edge_index, edge_attr);

    // join
    cudaStreamWaitEvent(0, ev_gemm, 0);

    int nblk = (N_NODES + 7) / 8;   // 8 warps per block
    node_fused_kernel<<<nblk, 256>>>(W_e, att, bias, out);
}

// round 14
// speedup vs baseline: 1.2179x; 1.0389x over previous
#include <cuda_runtime.h>
#include <cuda_fp16.h>
#include <cuda_bf16.h>
#include <cstdint>

#define N_NODES 50000
#define E_EDGES 800000
#define DIM     256
#define NHEAD   8
#define SCAN_BLK 1024
#define NBLK_SCAN ((N_NODES + SCAN_BLK - 1) / SCAN_BLK)   // 49

// ---------------- device scratch (allocation-free rule: use globals) -------
__device__ int    g_deg[N_NODES];          // zero-init at load; node_fused re-zeroes
__device__ __half g_xl_h[(size_t)N_NODES * DIM];   // x @ W_l (fp16)
__device__ __half g_xr_h[(size_t)N_NODES * DIM];   // x @ W_r (fp16)
__device__ int    g_row_start[N_NODES];
__device__ int    g_fill[N_NODES];
__device__ uint4  g_csr_rec[E_EDGES];              // {src, ea0, ea1, 0} packed 16B
__device__ int    g_scan_tmp[N_NODES];
__device__ int    g_block_sums[64];
__device__ __half g_wl_ht[DIM * DIM];              // W_l^T in fp16 [n][k]
__device__ __half g_wr_ht[DIM * DIM];              // W_r^T in fp16 [n][k]

// ---------------- weight transpose-convert (both in one launch) -------------
__global__ void cvt_wt_both_kernel(const float* __restrict__ Wl,
                                   const float* __restrict__ Wr) {
    int i = blockIdx.x * blockDim.x + threadIdx.x;
    if (i >= 2 * DIM * DIM) return;
    int which = i >= DIM * DIM;
    int j = i - which * DIM * DIM;
    int n = j >> 8, k = j & 255;
    const float* W = which ? Wr : Wl;
    __half* Wt = which ? g_wr_ht : g_wl_ht;
    Wt[j] = __float2half_rn(W[k * DIM + n]);
}

// ---------------- degree count (g_deg pre-zeroed by previous call) ----------
__global__ void edge_stats_kernel(const int* __restrict__ edge_index) {
    int e = blockIdx.x * blockDim.x + threadIdx.x;
    if (e >= E_EDGES) return;
    atomicAdd(&g_deg[edge_index[E_EDGES + e]], 1);
}

// ---------------- scan phase 1: per-block scan -------------------------------
__global__ __launch_bounds__(SCAN_BLK)
void scan_phase1_kernel() {
    __shared__ int warp_sums[32];
    int tid = threadIdx.x;
    int lane = tid & 31;
    int wid = tid >> 5;
    int idx = blockIdx.x * SCAN_BLK + tid;

    int v = (idx < N_NODES) ? g_deg[idx] : 0;
    int incl = v;
#pragma unroll
    for (int off = 1; off < 32; off <<= 1) {
        int t = __shfl_up_sync(0xffffffffu, incl, off);
        if (lane >= off) incl += t;
    }
    if (lane == 31) warp_sums[wid] = incl;
    __syncthreads();
    if (wid == 0) {
        int w = warp_sums[lane];
        int wi = w;
#pragma unroll
        for (int off = 1; off < 32; off <<= 1) {
            int t = __shfl_up_sync(0xffffffffu, wi, off);
            if (lane >= off) wi += t;
        }
        warp_sums[lane] = wi - w;
        if (lane == 31) g_block_sums[blockIdx.x] = wi;
    }
    __syncthreads();
    if (idx < N_NODES)
        g_scan_tmp[idx] = warp_sums[wid] + incl - v;
}

// ---------------- scan phase 3: block-offset scan done redundantly per block
__global__ void scan_phase3_kernel() {
    __shared__ int s_off[64];
    int tid = threadIdx.x;
    if (tid < 32) {
        int lane = tid;
        int v0 = (lane < NBLK_SCAN) ? g_block_sums[lane] : 0;
        int v1 = (lane + 32 < NBLK_SCAN) ? g_block_sums[lane + 32] : 0;
        int i0 = v0;
#pragma unroll
        for (int off = 1; off < 32; off <<= 1) {
            int t = __shfl_up_sync(0xffffffffu, i0, off);
            if (lane >= off) i0 += t;
        }
        int total0 = __shfl_sync(0xffffffffu, i0, 31);
        int i1 = v1;
#pragma unroll
        for (int off = 1; off < 32; off <<= 1) {
            int t = __shfl_up_sync(0xffffffffu, i1, off);
            if (lane >= off) i1 += t;
        }
        s_off[lane]      = i0 - v0;
        s_off[lane + 32] = total0 + i1 - v1;
    }
    __syncthreads();
    int i = blockIdx.x * blockDim.x + tid;
    if (i >= N_NODES) return;
    int rs = g_scan_tmp[i] + s_off[i / SCAN_BLK];
    g_row_start[i] = rs;
    g_fill[i] = rs;
}

// ---------------- CSR fill (packed 16B records) ------------------------------
__global__ void csr_fill_kernel(const int* __restrict__ edge_index,
                                const float* __restrict__ edge_attr) {
    int e = blockIdx.x * blockDim.x + threadIdx.x;
    if (e >= E_EDGES) return;
    int d = edge_index[E_EDGES + e];
    int pos = atomicAdd(&g_fill[d], 1);
    uint4 r;
    r.x = (unsigned)edge_index[e];
    r.y = __float_as_uint(edge_attr[2 * e]);
    r.z = __float_as_uint(edge_attr[2 * e + 1]);
    r.w = 0;
    g_csr_rec[pos] = r;
}

// ============================================================================
// FP16 tensor-core dual GEMM, fp32 A with fused fp16 convert in the loader.
// A = x [M][256] fp32 (converted to half in regs, STS half4).
// B = W^T [n][k] half (cp.async). BM=BN=128, BK=32, PITCH=40, ldmatrix frags.
// ============================================================================
#define GBM 128
#define GBN 128
#define GBK 32
#define PITCH 40

__device__ __forceinline__ void mma_f16(float4& d, const uint32_t* a, const uint32_t* b) {
    asm volatile(
        "mma.sync.aligned.m16n8k16.row.col.f32.f16.f16.f32 "
        "{%0,%1,%2,%3}, {%4,%5,%6,%7}, {%8,%9}, {%0,%1,%2,%3};"
        : "+f"(d.x), "+f"(d.y), "+f"(d.z), "+f"(d.w)
        : "r"(a[0]), "r"(a[1]), "r"(a[2]), "r"(a[3]), "r"(b[0]), "r"(b[1]));
}

__device__ __forceinline__ void ldsm_x4(uint32_t& r0, uint32_t& r1, uint32_t& r2, uint32_t& r3,
                                        uint32_t addr) {
    asm volatile("ldmatrix.sync.aligned.m8n8.x4.shared.b16 {%0,%1,%2,%3}, [%4];"
                 : "=r"(r0), "=r"(r1), "=r"(r2), "=r"(r3) : "r"(addr));
}

__device__ __forceinline__ void cp_async16(uint32_t smem_dst, const void* gmem_src, int src_bytes) {
    asm volatile("cp.async.cg.shared.global [%0], [%1], 16, %2;"
                 :: "r"(smem_dst), "l"(gmem_src), "r"(src_bytes));
}
__device__ __forceinline__ void cp_commit() { asm volatile("cp.async.commit_group;"); }
template<int NN> __device__ __forceinline__ void cp_wait() {
    asm volatile("cp.async.wait_group %0;" :: "n"(NN));
}

__device__ __forceinline__ uint32_t pack_h2(float a, float b) {
    __half2 h = __floats2half2_rn(a, b);
    return *(uint32_t*)&h;
}

__global__ __launch_bounds__(256, 2)
void gemm_f16_kernel(const float* __restrict__ A32,
                     int M) {
    __shared__ __half As[2][GBM * PITCH];
    __shared__ __half Bs[2][GBN * PITCH];

    const int tid  = threadIdx.x;
    const int wid  = tid >> 5;
    const int lane = tid & 31;
    const int g    = lane >> 2;
    const int tg   = lane & 3;

    const int warpM = wid & 1;
    const int warpN = wid >> 1;

    const int bm = blockIdx.x * GBM;
    const int bn = blockIdx.y * GBN;
    const __half* B = (blockIdx.z == 0) ? g_wl_ht : g_wr_ht;
    __half* Cout = (blockIdx.z == 0) ? g_xl_h : g_xr_h;

    // ldmatrix per-lane geometry
    const int rowA = (lane & 7) + 8 * ((lane >> 3) & 1);
    const int colA = (lane >> 4) * 8;
    const int qb   = lane >> 3;
    const int rowB = (lane & 7) + ((qb >> 1) * 8);
    const int colB = (qb & 1) * 8;

    uint32_t asBase[2], bsBase[2];
    asBase[0] = (uint32_t)__cvta_generic_to_shared(&As[0][0]);
    asBase[1] = (uint32_t)__cvta_generic_to_shared(&As[1][0]);
    bsBase[0] = (uint32_t)__cvta_generic_to_shared(&Bs[0][0]);
    bsBase[1] = (uint32_t)__cvta_generic_to_shared(&Bs[1][0]);

    // A loader mapping: chunk c in [0,1024): row = c>>3, c4 = c&7 (float4 idx)
    float4 a_ld[4];
    auto loadA_regs = [&](int kt) {
#pragma unroll
        for (int r = 0; r < 4; r++) {
            int c = tid + r * 256;
            int row = c >> 3, c4 = c & 7;
            int grow = (bm + row < M) ? (bm + row) : bm;
            a_ld[r] = *(const float4*)&A32[(size_t)grow * DIM + kt + c4 * 4];
        }
    };
    auto storeA_smem = [&](int st) {
#pragma unroll
        for (int r = 0; r < 4; r++) {
            int c = tid + r * 256;
            int row = c >> 3, c4 = c & 7;
            uint2 h4 = make_uint2(pack_h2(a_ld[r].x, a_ld[r].y),
                                  pack_h2(a_ld[r].z, a_ld[r].w));
            *(uint2*)&As[st][row * PITCH + c4 * 4] = h4;
        }
    };
    auto loadB_tile = [&](int kt, int st) {
#pragma unroll
        for (int r = 0; r < 2; r++) {
            int f = tid + r * 256;
            int row = f >> 2, c = f & 3;
            const __half* srcB = &B[(size_t)(bn + row) * DIM + kt + c * 8];
            uint32_t dstB = (uint32_t)__cvta_generic_to_shared(&Bs[st][row * PITCH + c * 8]);
            cp_async16(dstB, srcB, 16);
        }
        cp_commit();
    };

    float4 acc[4][4];
#pragma unroll
    for (int i = 0; i < 4; i++)
#pragma unroll
        for (int j = 0; j < 4; j++) acc[i][j] = make_float4(0.f, 0.f, 0.f, 0.f);

    const int NITER = DIM / GBK;   // 8

    // prologue: tile 0
    loadA_regs(0);
    loadB_tile(0, 0);
    storeA_smem(0);
    cp_wait<0>();
    __syncthreads();

    for (int it = 0; it < NITER; it++) {
        int st = it & 1;
        if (it + 1 < NITER) {
            loadA_regs((it + 1) * GBK);       // LDG in flight during compute
            loadB_tile((it + 1) * GBK, st ^ 1);
        }

#pragma unroll
        for (int ks = 0; ks < 2; ks++) {
            int k0 = ks * 16;
            uint32_t af[4][4];
#pragma unroll
            for (int mt = 0; mt < 4; mt++) {
                int m0 = warpM * 64 + mt * 16;
                uint32_t addr = asBase[st] + 2u * ((m0 + rowA) * PITCH + k0 + colA);
                ldsm_x4(af[mt][0], af[mt][1], af[mt][2], af[mt][3], addr);
            }
            uint32_t bf[4][2];
#pragma unroll
            for (int ntp = 0; ntp < 2; ntp++) {
                int n0 = warpN * 32 + ntp * 16;
                uint32_t addr = bsBase[st] + 2u * ((n0 + rowB) * PITCH + k0 + colB);
                ldsm_x4(bf[2 * ntp][0], bf[2 * ntp][1], bf[2 * ntp + 1][0], bf[2 * ntp + 1][1], addr);
            }
#pragma unroll
            for (int mt = 0; mt < 4; mt++)
#pragma unroll
                for (int nt = 0; nt < 4; nt++)
                    mma_f16(acc[mt][nt], af[mt], bf[nt]);
        }

        if (it + 1 < NITER) {
            storeA_smem(st ^ 1);   // buffer st^1 free (consumed before last sync)
            cp_wait<0>();
        }
        __syncthreads();
    }

#pragma unroll
    for (int mt = 0; mt < 4; mt++) {
        int r0 = bm + warpM * 64 + mt * 16 + g;
        int r1 = r0 + 8;
#pragma unroll
        for (int nt = 0; nt < 4; nt++) {
            int col = bn + warpN * 32 + nt * 8 + tg * 2;
            if (r0 < M)
                *(__half2*)&Cout[(size_t)r0 * DIM + col] = __floats2half2_rn(acc[mt][nt].x, acc[mt][nt].y);
            if (r1 < M)
                *(__half2*)&Cout[(size_t)r1 * DIM + col] = __floats2half2_rn(acc[mt][nt].z, acc[mt][nt].w);
        }
    }
}

// ============================================================================
// node-centric fused pass: warp per node, depth-1 prefetch. loop_attr computed
// in-register; self-loop last; att pre-scaled by log2(e) -> exp2f. No atomics.
// Zeroes g_deg[n] at the end (replaces zero_kernel; deterministic across calls).
// ============================================================================
__global__ __launch_bounds__(256)
void node_fused_kernel(const float* __restrict__ W_e,
                       const float* __restrict__ att,
                       const float* __restrict__ bias,
                       float* __restrict__ out) {
    __shared__ float sWe0[DIM];
    __shared__ float sWe1[DIM];
    __shared__ float sAtt[DIM];
    __shared__ float sBias[DIM];
    for (int i = threadIdx.x; i < DIM; i += blockDim.x) {
        sWe0[i] = W_e[i];
        sWe1[i] = W_e[DIM + i];
        sAtt[i] = att[i] * 1.4426950408889634f;   // fold log2(e): exp(p)=exp2(p')
        sBias[i] = bias[i];
    }
    __syncthreads();

    int warp = (int)((blockIdx.x * (size_t)blockDim.x + threadIdx.x) >> 5);
    int lane = threadIdx.x & 31;
    if (warp >= N_NODES) return;
    int n = warp;
    int ch0 = lane * 8;

    float xr[8];
    {
        uint4 rv = *(const uint4*)&g_xr_h[(size_t)n * DIM + ch0];
        const __half2* rh = (const __half2*)&rv;
#pragma unroll
        for (int j = 0; j < 4; j++) {
            float2 f = __half22float2(rh[j]);
            xr[2 * j] = f.x; xr[2 * j + 1] = f.y;
        }
    }

    float we0[8], we1[8], av[8];
#pragma unroll
    for (int j = 0; j < 8; j++) {
        we0[j] = sWe0[ch0 + j];
        we1[j] = sWe1[ch0 + j];
        av[j]  = sAtt[ch0 + j];
    }

    float acc[8] = {0.f, 0.f, 0.f, 0.f, 0.f, 0.f, 0.f, 0.f};
    float denom = 0.f;
    float eas0 = 0.f, eas1 = 0.f;

    int row = g_row_start[n];
    int deg = g_deg[n];

    if (deg > 0) {
        uint4 rec = g_csr_rec[row];
        float ea0_cur = __uint_as_float(rec.y);
        float ea1_cur = __uint_as_float(rec.z);
        uint4 lv_cur  = *(const uint4*)&g_xl_h[(size_t)rec.x * DIM + ch0];

        for (int i = 0; i < deg; i++) {
            float ea0_nxt = 0.f, ea1_nxt = 0.f; uint4 lv_nxt;
            if (i + 1 < deg) {
                uint4 rn = g_csr_rec[row + i + 1];
                ea0_nxt = __uint_as_float(rn.y);
                ea1_nxt = __uint_as_float(rn.z);
                lv_nxt = *(const uint4*)&g_xl_h[(size_t)rn.x * DIM + ch0];
            }

            float xl[8];
            {
                const __half2* lh = (const __half2*)&lv_cur;
#pragma unroll
                for (int j = 0; j < 4; j++) {
                    float2 f = __half22float2(lh[j]);
                    xl[2 * j] = f.x; xl[2 * j + 1] = f.y;
                }
            }
            float p = 0.f;
#pragma unroll
            for (int j = 0; j < 8; j++) {
                float m = xl[j] + xr[j] + ea0_cur * we0[j] + ea1_cur * we1[j];
                m = (m > 0.f) ? m : 0.2f * m;       // leaky relu
                p += m * av[j];
            }
            p += __shfl_xor_sync(0xffffffffu, p, 1);
            p += __shfl_xor_sync(0xffffffffu, p, 2);

            float ex = exp2f(p);
            denom += ex;
            eas0 += ea0_cur;
            eas1 += ea1_cur;
#pragma unroll
            for (int j = 0; j < 8; j++) acc[j] += ex * xl[j];

            ea0_cur = ea0_nxt; ea1_cur = ea1_nxt; lv_cur = lv_nxt;
        }
    }

    // self loop (loop_attr = mean incoming ea)
    {
        float invc = 1.0f / fmaxf((float)deg, 1.0f);
        float ea0 = eas0 * invc;
        float ea1 = eas1 * invc;
        uint4 lv = *(const uint4*)&g_xl_h[(size_t)n * DIM + ch0];
        const __half2* lh = (const __half2*)&lv;
        float xl[8];
#pragma unroll
        for (int j = 0; j < 4; j++) {
            float2 f = __half22float2(lh[j]);
            xl[2 * j] = f.x; xl[2 * j + 1] = f.y;
        }
        float p = 0.f;
#pragma unroll
        for (int j = 0; j < 8; j++) {
            float m = xl[j] + xr[j] + ea0 * we0[j] + ea1 * we1[j];
            m = (m > 0.f) ? m : 0.2f * m;
            p += m * av[j];
        }
        p += __shfl_xor_sync(0xffffffffu, p, 1);
        p += __shfl_xor_sync(0xffffffffu, p, 2);
        float ex = exp2f(p);
        denom += ex;
#pragma unroll
        for (int j = 0; j < 8; j++) acc[j] += ex * xl[j];
    }

    float inv = 1.0f / denom;
    float4 o0 = make_float4(acc[0] * inv + sBias[ch0 + 0], acc[1] * inv + sBias[ch0 + 1],
                            acc[2] * inv + sBias[ch0 + 2], acc[3] * inv + sBias[ch0 + 3]);
    float4 o1 = make_float4(acc[4] * inv + sBias[ch0 + 4], acc[5] * inv + sBias[ch0 + 5],
                            acc[6] * inv + sBias[ch0 + 6], acc[7] * inv + sBias[ch0 + 7]);
    *(float4*)&out[(size_t)n * DIM + ch0]     = o0;
    *(float4*)&out[(size_t)n * DIM + ch0 + 4] = o1;

    // reset degree for next graph replay (replaces zero_kernel)
    if (lane == 0) g_deg[n] = 0;
}

// ---------------- launch: fork GEMM branch onto a side stream ---------------
extern "C" void kernel_launch(void* const* d_in, const int* in_sizes, int n_in,
                              void* d_out, int out_size) {
    const float* x          = (const float*)d_in[0];
    const int*   edge_index = (const int*)  d_in[1];
    const float* edge_attr  = (const float*)d_in[2];
    const float* W_l        = (const float*)d_in[3];
    const float* W_r        = (const float*)d_in[4];
    const float* W_e        = (const float*)d_in[5];
    const float* att        = (const float*)d_in[6];
    const float* bias       = (const float*)d_in[7];
    float* out = (float*)d_out;

    cudaStream_t s1;
    cudaStreamCreateWithFlags(&s1, cudaStreamNonBlocking);
    cudaEvent_t ev_fork, ev_gemm;
    cudaEventCreateWithFlags(&ev_fork, cudaEventDisableTiming);
    cudaEventCreateWithFlags(&ev_gemm, cudaEventDisableTiming);

    // fork
    cudaEventRecord(ev_fork, 0);
    cudaStreamWaitEvent(s1, ev_fork, 0);

    // branch A (side stream): weight convert + dual GEMM (x converted in-loader)
    cvt_wt_both_kernel<<<(2 * DIM * DIM + 255) / 256, 256, 0, s1>>>(W_l, W_r);
    dim3 ggrid((N_NODES + GBM - 1) / GBM, DIM / GBN, 2);
    gemm_f16_kernel<<<ggrid, 256, 0, s1>>>(x, N_NODES);
    cudaEventRecord(ev_gemm, s1);

    // branch B (capture stream): CSR build (g_deg pre-zeroed by prior call)
    edge_stats_kernel<<<(E_EDGES + 511) / 512, 512>>>(edge_index);
    scan_phase1_kernel<<<NBLK_SCAN, SCAN_BLK>>>();
    scan_phase3_kernel<<<(N_NODES + 255) / 256, 256>>>();
    csr_fill_kernel<<<(E_EDGES + 255) / 256, 256>>>(edge_index, edge_attr);

    // join
    cudaStreamWaitEvent(0, ev_gemm, 0);

    int nblk = (N_NODES + 7) / 8;   // 8 warps per block
    node_fused_kernel<<<nblk, 256>>>(W_e, att, bias, out);
}

// round 15
// speedup vs baseline: 1.2681x; 1.0413x over previous
#include <cuda_runtime.h>
#include <cuda_fp16.h>
#include <cuda_bf16.h>
#include <cstdint>

#define N_NODES 50000
#define E_EDGES 800000
#define DIM     256
#define NHEAD   8
#define SCAN_BLK 1024
#define NBLK_SCAN ((N_NODES + SCAN_BLK - 1) / SCAN_BLK)   // 49

// ---------------- device scratch (allocation-free rule: use globals) -------
__device__ int    g_deg[N_NODES];          // zero-init at load; node_fused re-zeroes
__device__ __half g_xl_h[(size_t)N_NODES * DIM];   // x @ W_l (fp16)
__device__ __half g_xr_h[(size_t)N_NODES * DIM];   // x @ W_r (fp16)
__device__ int    g_row_start[N_NODES];
__device__ int    g_fill[N_NODES];
__device__ uint4  g_csr_rec[E_EDGES];              // {src, ea0, ea1, 0} packed 16B
__device__ int    g_scan_tmp[N_NODES];
__device__ int    g_block_sums[64];
__device__ __half g_wl_ht[DIM * DIM];              // W_l^T in fp16 [n][k]
__device__ __half g_wr_ht[DIM * DIM];              // W_r^T in fp16 [n][k]

// ---------------- weight transpose-convert (both in one launch) -------------
__global__ void cvt_wt_both_kernel(const float* __restrict__ Wl,
                                   const float* __restrict__ Wr) {
    int i = blockIdx.x * blockDim.x + threadIdx.x;
    if (i >= 2 * DIM * DIM) return;
    int which = i >= DIM * DIM;
    int j = i - which * DIM * DIM;
    int n = j >> 8, k = j & 255;
    const float* W = which ? Wr : Wl;
    __half* Wt = which ? g_wr_ht : g_wl_ht;
    Wt[j] = __float2half_rn(W[k * DIM + n]);
}

// ---------------- degree count (g_deg pre-zeroed by previous call) ----------
__global__ void edge_stats_kernel(const int* __restrict__ edge_index) {
    int e = blockIdx.x * blockDim.x + threadIdx.x;
    if (e >= E_EDGES) return;
    atomicAdd(&g_deg[edge_index[E_EDGES + e]], 1);
}

// ---------------- scan phase 1: per-block scan -------------------------------
__global__ __launch_bounds__(SCAN_BLK)
void scan_phase1_kernel() {
    __shared__ int warp_sums[32];
    int tid = threadIdx.x;
    int lane = tid & 31;
    int wid = tid >> 5;
    int idx = blockIdx.x * SCAN_BLK + tid;

    int v = (idx < N_NODES) ? g_deg[idx] : 0;
    int incl = v;
#pragma unroll
    for (int off = 1; off < 32; off <<= 1) {
        int t = __shfl_up_sync(0xffffffffu, incl, off);
        if (lane >= off) incl += t;
    }
    if (lane == 31) warp_sums[wid] = incl;
    __syncthreads();
    if (wid == 0) {
        int w = warp_sums[lane];
        int wi = w;
#pragma unroll
        for (int off = 1; off < 32; off <<= 1) {
            int t = __shfl_up_sync(0xffffffffu, wi, off);
            if (lane >= off) wi += t;
        }
        warp_sums[lane] = wi - w;
        if (lane == 31) g_block_sums[blockIdx.x] = wi;
    }
    __syncthreads();
    if (idx < N_NODES)
        g_scan_tmp[idx] = warp_sums[wid] + incl - v;
}

// ---------------- scan phase 3: block-offset scan done redundantly per block
__global__ void scan_phase3_kernel() {
    __shared__ int s_off[64];
    int tid = threadIdx.x;
    if (tid < 32) {
        int lane = tid;
        int v0 = (lane < NBLK_SCAN) ? g_block_sums[lane] : 0;
        int v1 = (lane + 32 < NBLK_SCAN) ? g_block_sums[lane + 32] : 0;
        int i0 = v0;
#pragma unroll
        for (int off = 1; off < 32; off <<= 1) {
            int t = __shfl_up_sync(0xffffffffu, i0, off);
            if (lane >= off) i0 += t;
        }
        int total0 = __shfl_sync(0xffffffffu, i0, 31);
        int i1 = v1;
#pragma unroll
        for (int off = 1; off < 32; off <<= 1) {
            int t = __shfl_up_sync(0xffffffffu, i1, off);
            if (lane >= off) i1 += t;
        }
        s_off[lane]      = i0 - v0;
        s_off[lane + 32] = total0 + i1 - v1;
    }
    __syncthreads();
    int i = blockIdx.x * blockDim.x + tid;
    if (i >= N_NODES) return;
    int rs = g_scan_tmp[i] + s_off[i / SCAN_BLK];
    g_row_start[i] = rs;
    g_fill[i] = rs;
}

// ---------------- CSR fill (packed 16B records) ------------------------------
__global__ void csr_fill_kernel(const int* __restrict__ edge_index,
                                const float* __restrict__ edge_attr) {
    int e = blockIdx.x * blockDim.x + threadIdx.x;
    if (e >= E_EDGES) return;
    int d = edge_index[E_EDGES + e];
    int pos = atomicAdd(&g_fill[d], 1);
    uint4 r;
    r.x = (unsigned)edge_index[e];
    r.y = __float_as_uint(edge_attr[2 * e]);
    r.z = __float_as_uint(edge_attr[2 * e + 1]);
    r.w = 0;
    g_csr_rec[pos] = r;
}

// ============================================================================
// FP16 tensor-core dual GEMM, fp32 A with fused fp16 convert in the loader.
// (unchanged from R14)
// ============================================================================
#define GBM 128
#define GBN 128
#define GBK 32
#define PITCH 40

__device__ __forceinline__ void mma_f16(float4& d, const uint32_t* a, const uint32_t* b) {
    asm volatile(
        "mma.sync.aligned.m16n8k16.row.col.f32.f16.f16.f32 "
        "{%0,%1,%2,%3}, {%4,%5,%6,%7}, {%8,%9}, {%0,%1,%2,%3};"
        : "+f"(d.x), "+f"(d.y), "+f"(d.z), "+f"(d.w)
        : "r"(a[0]), "r"(a[1]), "r"(a[2]), "r"(a[3]), "r"(b[0]), "r"(b[1]));
}

__device__ __forceinline__ void ldsm_x4(uint32_t& r0, uint32_t& r1, uint32_t& r2, uint32_t& r3,
                                        uint32_t addr) {
    asm volatile("ldmatrix.sync.aligned.m8n8.x4.shared.b16 {%0,%1,%2,%3}, [%4];"
                 : "=r"(r0), "=r"(r1), "=r"(r2), "=r"(r3) : "r"(addr));
}

__device__ __forceinline__ void cp_async16(uint32_t smem_dst, const void* gmem_src, int src_bytes) {
    asm volatile("cp.async.cg.shared.global [%0], [%1], 16, %2;"
                 :: "r"(smem_dst), "l"(gmem_src), "r"(src_bytes));
}
__device__ __forceinline__ void cp_commit() { asm volatile("cp.async.commit_group;"); }
template<int NN> __device__ __forceinline__ void cp_wait() {
    asm volatile("cp.async.wait_group %0;" :: "n"(NN));
}

__device__ __forceinline__ uint32_t pack_h2(float a, float b) {
    __half2 h = __floats2half2_rn(a, b);
    return *(uint32_t*)&h;
}

__global__ __launch_bounds__(256, 2)
void gemm_f16_kernel(const float* __restrict__ A32,
                     int M) {
    __shared__ __half As[2][GBM * PITCH];
    __shared__ __half Bs[2][GBN * PITCH];

    const int tid  = threadIdx.x;
    const int wid  = tid >> 5;
    const int lane = tid & 31;
    const int g    = lane >> 2;
    const int tg   = lane & 3;

    const int warpM = wid & 1;
    const int warpN = wid >> 1;

    const int bm = blockIdx.x * GBM;
    const int bn = blockIdx.y * GBN;
    const __half* B = (blockIdx.z == 0) ? g_wl_ht : g_wr_ht;
    __half* Cout = (blockIdx.z == 0) ? g_xl_h : g_xr_h;

    const int rowA = (lane & 7) + 8 * ((lane >> 3) & 1);
    const int colA = (lane >> 4) * 8;
    const int qb   = lane >> 3;
    const int rowB = (lane & 7) + ((qb >> 1) * 8);
    const int colB = (qb & 1) * 8;

    uint32_t asBase[2], bsBase[2];
    asBase[0] = (uint32_t)__cvta_generic_to_shared(&As[0][0]);
    asBase[1] = (uint32_t)__cvta_generic_to_shared(&As[1][0]);
    bsBase[0] = (uint32_t)__cvta_generic_to_shared(&Bs[0][0]);
    bsBase[1] = (uint32_t)__cvta_generic_to_shared(&Bs[1][0]);

    float4 a_ld[4];
    auto loadA_regs = [&](int kt) {
#pragma unroll
        for (int r = 0; r < 4; r++) {
            int c = tid + r * 256;
            int row = c >> 3, c4 = c & 7;
            int grow = (bm + row < M) ? (bm + row) : bm;
            a_ld[r] = *(const float4*)&A32[(size_t)grow * DIM + kt + c4 * 4];
        }
    };
    auto storeA_smem = [&](int st) {
#pragma unroll
        for (int r = 0; r < 4; r++) {
            int c = tid + r * 256;
            int row = c >> 3, c4 = c & 7;
            uint2 h4 = make_uint2(pack_h2(a_ld[r].x, a_ld[r].y),
                                  pack_h2(a_ld[r].z, a_ld[r].w));
            *(uint2*)&As[st][row * PITCH + c4 * 4] = h4;
        }
    };
    auto loadB_tile = [&](int kt, int st) {
#pragma unroll
        for (int r = 0; r < 2; r++) {
            int f = tid + r * 256;
            int row = f >> 2, c = f & 3;
            const __half* srcB = &B[(size_t)(bn + row) * DIM + kt + c * 8];
            uint32_t dstB = (uint32_t)__cvta_generic_to_shared(&Bs[st][row * PITCH + c * 8]);
            cp_async16(dstB, srcB, 16);
        }
        cp_commit();
    };

    float4 acc[4][4];
#pragma unroll
    for (int i = 0; i < 4; i++)
#pragma unroll
        for (int j = 0; j < 4; j++) acc[i][j] = make_float4(0.f, 0.f, 0.f, 0.f);

    const int NITER = DIM / GBK;   // 8

    loadA_regs(0);
    loadB_tile(0, 0);
    storeA_smem(0);
    cp_wait<0>();
    __syncthreads();

    for (int it = 0; it < NITER; it++) {
        int st = it & 1;
        if (it + 1 < NITER) {
            loadA_regs((it + 1) * GBK);
            loadB_tile((it + 1) * GBK, st ^ 1);
        }

#pragma unroll
        for (int ks = 0; ks < 2; ks++) {
            int k0 = ks * 16;
            uint32_t af[4][4];
#pragma unroll
            for (int mt = 0; mt < 4; mt++) {
                int m0 = warpM * 64 + mt * 16;
                uint32_t addr = asBase[st] + 2u * ((m0 + rowA) * PITCH + k0 + colA);
                ldsm_x4(af[mt][0], af[mt][1], af[mt][2], af[mt][3], addr);
            }
            uint32_t bf[4][2];
#pragma unroll
            for (int ntp = 0; ntp < 2; ntp++) {
                int n0 = warpN * 32 + ntp * 16;
                uint32_t addr = bsBase[st] + 2u * ((n0 + rowB) * PITCH + k0 + colB);
                ldsm_x4(bf[2 * ntp][0], bf[2 * ntp][1], bf[2 * ntp + 1][0], bf[2 * ntp + 1][1], addr);
            }
#pragma unroll
            for (int mt = 0; mt < 4; mt++)
#pragma unroll
                for (int nt = 0; nt < 4; nt++)
                    mma_f16(acc[mt][nt], af[mt], bf[nt]);
        }

        if (it + 1 < NITER) {
            storeA_smem(st ^ 1);
            cp_wait<0>();
        }
        __syncthreads();
    }

#pragma unroll
    for (int mt = 0; mt < 4; mt++) {
        int r0 = bm + warpM * 64 + mt * 16 + g;
        int r1 = r0 + 8;
#pragma unroll
        for (int nt = 0; nt < 4; nt++) {
            int col = bn + warpN * 32 + nt * 8 + tg * 2;
            if (r0 < M)
                *(__half2*)&Cout[(size_t)r0 * DIM + col] = __floats2half2_rn(acc[mt][nt].x, acc[mt][nt].y);
            if (r1 < M)
                *(__half2*)&Cout[(size_t)r1 * DIM + col] = __floats2half2_rn(acc[mt][nt].z, acc[mt][nt].w);
        }
    }
}

// ============================================================================
// node-centric fused pass v6: warp per node, depth-1 prefetch, HALF2 score
// math (xl/xr stay fp16; leaky = hmax2(m, 0.2*m)); exp/denom/acc in fp32.
// loop_attr in-register; att pre-scaled by log2(e); no atomics.
// ============================================================================
__global__ __launch_bounds__(256)
void node_fused_kernel(const float* __restrict__ W_e,
                       const float* __restrict__ att,
                       const float* __restrict__ bias,
                       float* __restrict__ out) {
    __shared__ float sWe0[DIM];
    __shared__ float sWe1[DIM];
    __shared__ float sAtt[DIM];
    __shared__ float sBias[DIM];
    for (int i = threadIdx.x; i < DIM; i += blockDim.x) {
        sWe0[i] = W_e[i];
        sWe1[i] = W_e[DIM + i];
        sAtt[i] = att[i] * 1.4426950408889634f;   // fold log2(e)
        sBias[i] = bias[i];
    }
    __syncthreads();

    int warp = (int)((blockIdx.x * (size_t)blockDim.x + threadIdx.x) >> 5);
    int lane = threadIdx.x & 31;
    if (warp >= N_NODES) return;
    int n = warp;
    int ch0 = lane * 8;

    // per-lane constants in half2 (4 groups of 2 channels)
    __half2 xr2[4], we0h[4], we1h[4], avh[4];
    {
        uint4 rv = *(const uint4*)&g_xr_h[(size_t)n * DIM + ch0];
        const __half2* rh = (const __half2*)&rv;
#pragma unroll
        for (int q = 0; q < 4; q++) {
            xr2[q]  = rh[q];
            we0h[q] = __floats2half2_rn(sWe0[ch0 + 2 * q], sWe0[ch0 + 2 * q + 1]);
            we1h[q] = __floats2half2_rn(sWe1[ch0 + 2 * q], sWe1[ch0 + 2 * q + 1]);
            avh[q]  = __floats2half2_rn(sAtt[ch0 + 2 * q], sAtt[ch0 + 2 * q + 1]);
        }
    }
    const __half2 c02 = __float2half2_rn(0.2f);

    float acc[8] = {0.f, 0.f, 0.f, 0.f, 0.f, 0.f, 0.f, 0.f};
    float denom = 0.f;
    float eas0 = 0.f, eas1 = 0.f;

    int row = g_row_start[n];
    int deg = g_deg[n];

    // process one edge given its ea (fp32) and xl payload (4 half2)
    auto do_edge = [&](float ea0, float ea1, uint4 lv) {
        const __half2* lh = (const __half2*)&lv;
        __half2 e0h = __float2half2_rn(ea0);
        __half2 e1h = __float2half2_rn(ea1);
        __half2 p2 = __float2half2_rn(0.f);
        float xl[8];
#pragma unroll
        for (int q = 0; q < 4; q++) {
            __half2 m = __hadd2(lh[q], xr2[q]);
            m = __hfma2(e0h, we0h[q], m);
            m = __hfma2(e1h, we1h[q], m);
            m = __hmax2(m, __hmul2(m, c02));       // leaky relu
            p2 = __hfma2(m, avh[q], p2);
            float2 f = __half22float2(lh[q]);       // xl fp32 for acc
            xl[2 * q] = f.x; xl[2 * q + 1] = f.y;
        }
        float2 pf = __half22float2(p2);
        float p = pf.x + pf.y;
        p += __shfl_xor_sync(0xffffffffu, p, 1);
        p += __shfl_xor_sync(0xffffffffu, p, 2);

        float ex = exp2f(p);
        denom += ex;
#pragma unroll
        for (int j = 0; j < 8; j++) acc[j] += ex * xl[j];
        return ex;
    };

    if (deg > 0) {
        uint4 rec = g_csr_rec[row];
        float ea0_cur = __uint_as_float(rec.y);
        float ea1_cur = __uint_as_float(rec.z);
        uint4 lv_cur  = *(const uint4*)&g_xl_h[(size_t)rec.x * DIM + ch0];

        for (int i = 0; i < deg; i++) {
            float ea0_nxt = 0.f, ea1_nxt = 0.f; uint4 lv_nxt;
            if (i + 1 < deg) {
                uint4 rn = g_csr_rec[row + i + 1];
                ea0_nxt = __uint_as_float(rn.y);
                ea1_nxt = __uint_as_float(rn.z);
                lv_nxt = *(const uint4*)&g_xl_h[(size_t)rn.x * DIM + ch0];
            }

            do_edge(ea0_cur, ea1_cur, lv_cur);
            eas0 += ea0_cur;
            eas1 += ea1_cur;

            ea0_cur = ea0_nxt; ea1_cur = ea1_nxt; lv_cur = lv_nxt;
        }
    }

    // self loop (loop_attr = mean incoming ea)
    {
        float invc = 1.0f / fmaxf((float)deg, 1.0f);
        uint4 lv = *(const uint4*)&g_xl_h[(size_t)n * DIM + ch0];
        do_edge(eas0 * invc, eas1 * invc, lv);
    }

    float inv = 1.0f / denom;
    float4 o0 = make_float4(acc[0] * inv + sBias[ch0 + 0], acc[1] * inv + sBias[ch0 + 1],
                            acc[2] * inv + sBias[ch0 + 2], acc[3] * inv + sBias[ch0 + 3]);
    float4 o1 = make_float4(acc[4] * inv + sBias[ch0 + 4], acc[5] * inv + sBias[ch0 + 5],
                            acc[6] * inv + sBias[ch0 + 6], acc[7] * inv + sBias[ch0 + 7]);
    *(float4*)&out[(size_t)n * DIM + ch0]     = o0;
    *(float4*)&out[(size_t)n * DIM + ch0 + 4] = o1;

    if (lane == 0) g_deg[n] = 0;   // reset for next replay (replaces zero_kernel)
}

// ---------------- launch: fork GEMM branch onto a side stream ---------------
extern "C" void kernel_launch(void* const* d_in, const int* in_sizes, int n_in,
                              void* d_out, int out_size) {
    const float* x          = (const float*)d_in[0];
    const int*   edge_index = (const int*)  d_in[1];
    const float* edge_attr  = (const float*)d_in[2];
    const float* W_l        = (const float*)d_in[3];
    const float* W_r        = (const float*)d_in[4];
    const float* W_e        = (const float*)d_in[5];
    const float* att        = (const float*)d_in[6];
    const float* bias       = (const float*)d_in[7];
    float* out = (float*)d_out;

    cudaStream_t s1;
    cudaStreamCreateWithFlags(&s1, cudaStreamNonBlocking);
    cudaEvent_t ev_fork, ev_gemm;
    cudaEventCreateWithFlags(&ev_fork, cudaEventDisableTiming);
    cudaEventCreateWithFlags(&ev_gemm, cudaEventDisableTiming);

    // fork
    cudaEventRecord(ev_fork, 0);
    cudaStreamWaitEvent(s1, ev_fork, 0);

    // branch A (side stream): weight convert + dual GEMM (x converted in-loader)
    cvt_wt_both_kernel<<<(2 * DIM * DIM + 255) / 256, 256, 0, s1>>>(W_l, W_r);
    dim3 ggrid((N_NODES + GBM - 1) / GBM, DIM / GBN, 2);
    gemm_f16_kernel<<<ggrid, 256, 0, s1>>>(x, N_NODES);
    cudaEventRecord(ev_gemm, s1);

    // branch B (capture stream): CSR build (g_deg pre-zeroed by prior call)
    edge_stats_kernel<<<(E_EDGES + 511) / 512, 512>>>(edge_index);
    scan_phase1_kernel<<<NBLK_SCAN, SCAN_BLK>>>();
    scan_phase3_kernel<<<(N_NODES + 255) / 256, 256>>>();
    csr_fill_kernel<<<(E_EDGES + 255) / 256, 256>>>(edge_index, edge_attr);

    // join
    cudaStreamWaitEvent(0, ev_gemm, 0);

    int nblk = (N_NODES + 7) / 8;   // 8 warps per block
    node_fused_kernel<<<nblk, 256>>>(W_e, att, bias, out);
}